// round 1
// baseline (speedup 1.0000x reference)
#include <cuda_runtime.h>
#include <float.h>
#include <stdint.h>

#define BB 4
#define NN 4096
#define KK 40
#define BN_ (BB*NN)            // 16384
#define BNK (BB*NN*KK)         // 655360

// ---------------- static scratch (no allocations allowed) ----------------
__device__ float d_nrm[BN_];
__device__ int   d_idx[BNK];
__device__ float d_e [(size_t)BNK*128];   // edge features / hA / hB alias / h7
__device__ float d_t1[(size_t)BNK*64];    // conv outputs / conv6 out / h8
__device__ float d_t2[(size_t)BNK*64];    // conv outputs / hB
__device__ float d_x1[BN_*64];
__device__ float d_x2[BN_*64];
__device__ float d_x3[BN_*64];
__device__ float d_g [BB*1024];
__device__ float d_gpart[32*BB*1024];
__device__ float d_h9[(size_t)BN_*63];

// ---------------- squared norms ----------------
__global__ void nrm_kernel(const float* __restrict__ x, float* __restrict__ nrm){
    int i = blockIdx.x*256 + threadIdx.x;        // over B*N
    if (i >= BN_) return;
    int b = i >> 12, n = i & (NN-1);
    const float* xb = x + (size_t)b*3*NN;
    float a = xb[n], c = xb[NN+n], d = xb[2*NN+n];
    nrm[i] = a*a + c*c + d*d;
}

// ---------------- kNN: one block per query point ----------------
__global__ void __launch_bounds__(256) knn_kernel(const float* __restrict__ x,
                                                  const float* __restrict__ nrm,
                                                  int* __restrict__ idxo){
    __shared__ float pd[NN];
    __shared__ float segv[256];
    __shared__ int   segp[256];
    __shared__ float wv[8];
    __shared__ int   wp[8];
    __shared__ int   sh_win;
    int blk = blockIdx.x;
    int b = blk >> 12;
    int n = blk & (NN-1);
    int tid = threadIdx.x;
    const float* xb = x + (size_t)b*3*NN;
    const float* nb = nrm + b*NN;
    float qx = xb[n], qy = xb[NN+n], qz = xb[2*NN+n];
    float qn = nb[n];
    for (int i = tid; i < NN; i += 256){
        float d = 2.f*(qx*xb[i] + qy*xb[NN+i] + qz*xb[2*NN+i]) - qn - nb[i];
        pd[i] = d;
    }
    __syncthreads();
    {
        int base = tid*16;
        float v = pd[base]; int p = base;
        #pragma unroll
        for (int i=1;i<16;i++){ float t = pd[base+i]; if (t > v){ v=t; p=base+i; } }
        segv[tid]=v; segp[tid]=p;
    }
    __syncthreads();
    int* out = idxo + (size_t)blk*KK;
    for (int kk=0; kk<KK; kk++){
        float v = segv[tid]; int p = segp[tid];
        #pragma unroll
        for (int off=16; off>0; off>>=1){
            float ov = __shfl_down_sync(0xffffffffu, v, off);
            int   op = __shfl_down_sync(0xffffffffu, p, off);
            if (ov > v || (ov == v && op < p)){ v=ov; p=op; }
        }
        if ((tid & 31) == 0){ wv[tid>>5]=v; wp[tid>>5]=p; }
        __syncthreads();
        if (tid == 0){
            float bv = wv[0]; int bp = wp[0];
            #pragma unroll
            for (int w=1; w<8; w++){
                if (wv[w] > bv || (wv[w]==bv && wp[w]<bp)){ bv=wv[w]; bp=wp[w]; }
            }
            sh_win = bp;
            out[kk] = bp;
        }
        __syncthreads();
        int w = sh_win;
        if (tid == (w >> 4)){
            pd[w] = -FLT_MAX;
            int base = tid*16;
            float v2 = pd[base]; int p2 = base;
            #pragma unroll
            for (int i=1;i<16;i++){ float t=pd[base+i]; if (t>v2){v2=t;p2=base+i;} }
            segv[tid]=v2; segp[tid]=p2;
        }
        __syncthreads();
    }
}

// ---------------- edge features, stage 1 (3-dim coords -> 6 features) ------
__global__ void edge1_kernel(const float* __restrict__ x, const int* __restrict__ idx,
                             float* __restrict__ e){
    int t = blockIdx.x*256 + threadIdx.x;     // over B*N*K
    if (t >= BNK) return;
    int p = t / KK;                            // b*N+n
    int n = p & (NN-1);
    int b = p >> 12;
    int j = idx[t];
    const float* xb = x + (size_t)b*3*NN;
    float cx = xb[n],  cy = xb[NN+n],  cz = xb[2*NN+n];
    float nx = xb[j],  ny = xb[NN+j],  nz = xb[2*NN+j];
    float* ep = e + (size_t)t*6;
    ep[0]=nx-cx; ep[1]=ny-cy; ep[2]=nz-cz; ep[3]=cx; ep[4]=cy; ep[5]=cz;
}

// ---------------- edge features, 64-dim inputs -> 128 features -------------
__global__ void edge64_kernel(const float* __restrict__ f, const int* __restrict__ idx,
                              float* __restrict__ e){
    int t = blockIdx.x*256 + threadIdx.x;     // over B*N*K*64 = 41943040
    int c = t & 63;
    int r = t >> 6;                            // edge row in [0, BNK)
    int p = r / KK;                            // b*N+n
    int b = p >> 12;
    int j = idx[r];
    float ctr = f[(size_t)p*64 + c];
    float nbr = f[((size_t)(b<<12) + j)*64 + c];
    float* ep = e + (size_t)r*128;
    ep[c]      = nbr - ctr;
    ep[64 + c] = ctr;
}

// ---------------- generic fp32 GEMM + BN + leaky-relu ----------------------
// C[m,n] = act( s[n] * sum_k A[m,k]*W[n,k] + b[n] ),  act = leaky_relu(.,leak)
// M must be a multiple of 64. N,K arbitrary (guarded).
__global__ void __launch_bounds__(256) gemm_bn_act(
        const float* __restrict__ A, const float* __restrict__ W,
        const float* __restrict__ s, const float* __restrict__ bias,
        float* __restrict__ C, int M, int Kd, int Nd, float leak)
{
    __shared__ float As[16][68];
    __shared__ float Ws[16][68];
    int m0 = blockIdx.x * 64;
    int n0 = blockIdx.y * 64;
    int tid = threadIdx.x;
    int lc = tid & 15;      // k within tile
    int lr = tid >> 4;      // 0..15
    int tx = tid & 15;
    int ty = tid >> 4;
    float acc[4][4];
    #pragma unroll
    for (int i=0;i<4;i++)
        #pragma unroll
        for (int j=0;j<4;j++) acc[i][j]=0.f;

    int nkt = (Kd + 15) >> 4;
    for (int kt = 0; kt < nkt; kt++){
        int k0 = kt*16;
        int k  = k0 + lc;
        #pragma unroll
        for (int j=0;j<4;j++){
            int m = m0 + lr + 16*j;
            float v = 0.f;
            if (k < Kd) v = A[(size_t)m*Kd + k];
            As[lc][lr + 16*j] = v;
        }
        #pragma unroll
        for (int j=0;j<4;j++){
            int n = n0 + lr + 16*j;
            float v = 0.f;
            if (k < Kd && n < Nd) v = W[(size_t)n*Kd + k];
            Ws[lc][lr + 16*j] = v;
        }
        __syncthreads();
        #pragma unroll
        for (int kk=0;kk<16;kk++){
            float4 a4 = *(const float4*)&As[kk][ty*4];
            float4 b4 = *(const float4*)&Ws[kk][tx*4];
            float ar[4] = {a4.x,a4.y,a4.z,a4.w};
            float br[4] = {b4.x,b4.y,b4.z,b4.w};
            #pragma unroll
            for (int i=0;i<4;i++)
                #pragma unroll
                for (int j=0;j<4;j++)
                    acc[i][j] += ar[i]*br[j];
        }
        __syncthreads();
    }
    #pragma unroll
    for (int i=0;i<4;i++){
        int m = m0 + ty*4 + i;
        #pragma unroll
        for (int j=0;j<4;j++){
            int n = n0 + tx*4 + j;
            if (n < Nd){
                float z = acc[i][j];
                float sc = s ? s[n] : 1.f;
                float bb = bias ? bias[n] : 0.f;
                z = z*sc + bb;
                C[(size_t)m*Nd + n] = (z > 0.f) ? z : leak*z;
            }
        }
    }
}

// ---------------- max over k neighbors -------------------------------------
__global__ void maxk_kernel(const float* __restrict__ t, float* __restrict__ o){
    int i = blockIdx.x*256 + threadIdx.x;     // over B*N*64 = 1048576
    int c = i & 63;
    int p = i >> 6;
    const float* tp = t + (size_t)p*KK*64 + c;
    float m = tp[0];
    #pragma unroll 8
    for (int k=1;k<KK;k++) m = fmaxf(m, tp[(size_t)k*64]);
    o[i] = m;
}

// ---------------- concat [x1,x2,x3] -> 192 ---------------------------------
__global__ void concatA_kernel(const float* __restrict__ x1, const float* __restrict__ x2,
                               const float* __restrict__ x3, float* __restrict__ h){
    int i = blockIdx.x*256 + threadIdx.x;     // over BN_*192
    int c = i % 192;
    int p = i / 192;
    float v;
    if (c < 64)       v = x1[p*64 + c];
    else if (c < 128) v = x2[p*64 + c - 64];
    else              v = x3[p*64 + c - 128];
    h[i] = v;
}

// ---------------- max over N (partial + reduce) ----------------------------
__global__ void maxn_part(const float* __restrict__ t6, float* __restrict__ gpart){
    int i = blockIdx.x*256 + threadIdx.x;     // over B*1024*32 = 131072
    int c = i & 1023;
    int rest = i >> 10;
    int b = rest & 3;
    int sg = rest >> 2;                        // 0..31
    const float* tp = t6 + ((size_t)b*NN + sg*128)*1024 + c;
    float m = -FLT_MAX;
    for (int r=0;r<128;r++) m = fmaxf(m, tp[(size_t)r*1024]);
    gpart[(size_t)sg*(BB*1024) + b*1024 + c] = m;
}
__global__ void maxn_red(const float* __restrict__ gpart, float* __restrict__ g){
    int i = blockIdx.x*256 + threadIdx.x;     // over B*1024
    if (i >= BB*1024) return;
    float m = -FLT_MAX;
    #pragma unroll
    for (int sg=0; sg<32; sg++) m = fmaxf(m, gpart[(size_t)sg*(BB*1024) + i]);
    g[i] = m;
}

// ---------------- concat [g, x1, x2, x3] -> 1216 ---------------------------
__global__ void concatB_kernel(const float* __restrict__ g, const float* __restrict__ x1,
                               const float* __restrict__ x2, const float* __restrict__ x3,
                               float* __restrict__ h){
    int i = blockIdx.x*256 + threadIdx.x;     // over BN_*1216 = 19922944
    int c = i % 1216;
    int p = i / 1216;
    int b = p >> 12;
    float v;
    if (c < 1024)       v = g[b*1024 + c];
    else {
        int c2 = c - 1024;
        if (c2 < 64)       v = x1[p*64 + c2];
        else if (c2 < 128) v = x2[p*64 + c2 - 64];
        else               v = x3[p*64 + c2 - 128];
    }
    h[i] = v;
}

// ---------------- final transpose (B,N,63) -> (B,63,N) ---------------------
__global__ void transpose_out(const float* __restrict__ h9, float* __restrict__ out){
    int i = blockIdx.x*256 + threadIdx.x;     // over BN_*63 = 1032192
    int o = i % 63;
    int p = i / 63;
    int b = p >> 12;
    int n = p & (NN-1);
    out[((size_t)b*63 + o)*NN + n] = h9[i];
}

// ---------------------------------------------------------------------------
extern "C" void kernel_launch(void* const* d_in, const int* in_sizes, int n_in,
                              void* d_out, int out_size){
    const float* x  = (const float*)d_in[0];
    const float* W1 = (const float*)d_in[1];
    const float* s1 = (const float*)d_in[2];
    const float* b1 = (const float*)d_in[3];
    const float* W2 = (const float*)d_in[4];
    const float* s2 = (const float*)d_in[5];
    const float* b2 = (const float*)d_in[6];
    const float* W3 = (const float*)d_in[7];
    const float* s3 = (const float*)d_in[8];
    const float* b3 = (const float*)d_in[9];
    const float* W4 = (const float*)d_in[10];
    const float* s4 = (const float*)d_in[11];
    const float* b4 = (const float*)d_in[12];
    const float* W5 = (const float*)d_in[13];
    const float* s5 = (const float*)d_in[14];
    const float* b5 = (const float*)d_in[15];
    const float* W6 = (const float*)d_in[16];
    const float* s6 = (const float*)d_in[17];
    const float* b6 = (const float*)d_in[18];
    const float* W7 = (const float*)d_in[19];
    const float* s7 = (const float*)d_in[20];
    const float* b7 = (const float*)d_in[21];
    const float* W8 = (const float*)d_in[22];
    const float* s8 = (const float*)d_in[23];
    const float* b8 = (const float*)d_in[24];
    const float* W9 = (const float*)d_in[25];
    const float* b9 = (const float*)d_in[26];
    float* out = (float*)d_out;

    float *nrm,*e,*t1,*t2,*x1,*x2,*x3,*g,*gpart,*h9; int* idx;
    cudaGetSymbolAddress((void**)&nrm,   d_nrm);
    cudaGetSymbolAddress((void**)&idx,   d_idx);
    cudaGetSymbolAddress((void**)&e,     d_e);
    cudaGetSymbolAddress((void**)&t1,    d_t1);
    cudaGetSymbolAddress((void**)&t2,    d_t2);
    cudaGetSymbolAddress((void**)&x1,    d_x1);
    cudaGetSymbolAddress((void**)&x2,    d_x2);
    cudaGetSymbolAddress((void**)&x3,    d_x3);
    cudaGetSymbolAddress((void**)&g,     d_g);
    cudaGetSymbolAddress((void**)&gpart, d_gpart);
    cudaGetSymbolAddress((void**)&h9,    d_h9);

    const float LK = 0.2f;

    nrm_kernel<<<64,256>>>(x, nrm);
    knn_kernel<<<BN_,256>>>(x, nrm, idx);

    // stage 1: edge conv (6 -> 64 -> 64) + max_k
    edge1_kernel<<<BNK/256,256>>>(x, idx, e);
    gemm_bn_act<<<dim3(BNK/64,1),256>>>(e,  W1, s1, b1, t1, BNK,   6,  64, LK);
    gemm_bn_act<<<dim3(BNK/64,1),256>>>(t1, W2, s2, b2, t2, BNK,  64,  64, LK);
    maxk_kernel<<<4096,256>>>(t2, x1);

    // stage 2: edge conv (128 -> 64 -> 64) + max_k
    edge64_kernel<<<163840,256>>>(x1, idx, e);
    gemm_bn_act<<<dim3(BNK/64,1),256>>>(e,  W3, s3, b3, t1, BNK, 128,  64, LK);
    gemm_bn_act<<<dim3(BNK/64,1),256>>>(t1, W4, s4, b4, t2, BNK,  64,  64, LK);
    maxk_kernel<<<4096,256>>>(t2, x2);

    // stage 3: edge conv (128 -> 64) + max_k
    edge64_kernel<<<163840,256>>>(x2, idx, e);
    gemm_bn_act<<<dim3(BNK/64,1),256>>>(e,  W5, s5, b5, t1, BNK, 128,  64, LK);
    maxk_kernel<<<4096,256>>>(t1, x3);

    // global embedding: concat(192) -> 1024 -> max over N
    concatA_kernel<<<12288,256>>>(x1, x2, x3, e);                 // hA in e
    gemm_bn_act<<<dim3(BN_/64,16),256>>>(e, W6, s6, b6, t1, BN_, 192, 1024, LK);
    maxn_part<<<512,256>>>(t1, gpart);
    maxn_red<<<16,256>>>(gpart, g);

    // head: concat(1216) -> 512 -> 256 -> 63 (+bias, no act) -> transpose
    concatB_kernel<<<77824,256>>>(g, x1, x2, x3, t2);             // hB in t2
    gemm_bn_act<<<dim3(BN_/64,8),256>>>(t2, W7, s7, b7, e,  BN_, 1216, 512, LK);   // h7 in e
    gemm_bn_act<<<dim3(BN_/64,4),256>>>(e,  W8, s8, b8, t1, BN_,  512, 256, LK);   // h8 in t1
    gemm_bn_act<<<dim3(BN_/64,1),256>>>(t1, W9, nullptr, b9, h9, BN_, 256, 63, 1.0f);
    transpose_out<<<4032,256>>>(h9, out);
}

// round 2
// speedup vs baseline: 2.0603x; 2.0603x over previous
#include <cuda_runtime.h>
#include <float.h>
#include <stdint.h>

#define NBB 4
#define NNN 4096
#define NKK 40
#define BN_ (NBB*NNN)            // 16384
#define BNK (BN_*NKK)            // 655360

// ---------------- static scratch ----------------
__device__ float    d_nrm[BN_];
__device__ int      d_idx[BNK];
__device__ float    d_xcat[(size_t)BN_*192];   // [x1|x2|x3] per point
__device__ float    d_PQ[(size_t)BN_*128];     // P (0..63) | Q (64..127)
__device__ float    d_h7[(size_t)BN_*512];
__device__ float    d_h8[(size_t)BN_*256];
__device__ float    d_Wpq[128*64];
__device__ unsigned d_gmax[NBB*1024];
__device__ float    d_Gb[NBB*512];

__device__ __forceinline__ unsigned enc_f(float f){
    unsigned u = __float_as_uint(f);
    return (u & 0x80000000u) ? ~u : (u | 0x80000000u);
}
__device__ __forceinline__ float dec_f(unsigned k){
    unsigned u = (k & 0x80000000u) ? (k & 0x7FFFFFFFu) : ~k;
    return __uint_as_float(u);
}

// ---------------- squared norms ----------------
__global__ void nrm_kernel(const float* __restrict__ x, float* __restrict__ nrm){
    int i = blockIdx.x*256 + threadIdx.x;
    if (i >= BN_) return;
    int b = i >> 12, n = i & (NNN-1);
    const float* xb = x + (size_t)b*3*NNN;
    float a = xb[n], c = xb[NNN+n], d = xb[2*NNN+n];
    nrm[i] = a*a + c*c + d*d;
}

// ---------------- kNN: one block per query point ----------------
__global__ void __launch_bounds__(256) knn_kernel(const float* __restrict__ x,
                                                  const float* __restrict__ nrm,
                                                  int* __restrict__ idxo){
    __shared__ float pd[NNN];
    __shared__ float segv[256];
    __shared__ int   segp[256];
    __shared__ float wv[8];
    __shared__ int   wp[8];
    __shared__ int   sh_win;
    int blk = blockIdx.x;
    int b = blk >> 12;
    int n = blk & (NNN-1);
    int tid = threadIdx.x;
    const float* xb = x + (size_t)b*3*NNN;
    const float* nb = nrm + b*NNN;
    float qx = xb[n], qy = xb[NNN+n], qz = xb[2*NNN+n];
    float qn = nb[n];
    for (int i = tid; i < NNN; i += 256){
        float d = 2.f*(qx*xb[i] + qy*xb[NNN+i] + qz*xb[2*NNN+i]) - qn - nb[i];
        pd[i] = d;
    }
    __syncthreads();
    {
        int base = tid*16;
        float v = pd[base]; int p = base;
        #pragma unroll
        for (int i=1;i<16;i++){ float t = pd[base+i]; if (t > v){ v=t; p=base+i; } }
        segv[tid]=v; segp[tid]=p;
    }
    __syncthreads();
    int* out = idxo + (size_t)blk*NKK;
    for (int kk=0; kk<NKK; kk++){
        float v = segv[tid]; int p = segp[tid];
        #pragma unroll
        for (int off=16; off>0; off>>=1){
            float ov = __shfl_down_sync(0xffffffffu, v, off);
            int   op = __shfl_down_sync(0xffffffffu, p, off);
            if (ov > v || (ov == v && op < p)){ v=ov; p=op; }
        }
        if ((tid & 31) == 0){ wv[tid>>5]=v; wp[tid>>5]=p; }
        __syncthreads();
        if (tid == 0){
            float bv = wv[0]; int bp = wp[0];
            #pragma unroll
            for (int w=1; w<8; w++){
                if (wv[w] > bv || (wv[w]==bv && wp[w]<bp)){ bv=wv[w]; bp=wp[w]; }
            }
            sh_win = bp;
            out[kk] = bp;
        }
        __syncthreads();
        int w = sh_win;
        if (tid == (w >> 4)){
            pd[w] = -FLT_MAX;
            int base = tid*16;
            float v2 = pd[base]; int p2 = base;
            #pragma unroll
            for (int i=1;i<16;i++){ float t=pd[base+i]; if (t>v2){v2=t;p2=base+i;} }
            segv[tid]=v2; segp[tid]=p2;
        }
        __syncthreads();
    }
}

// ---------------- P/Q from coords (stage 1) --------------------------------
__global__ void pq1_kernel(const float* __restrict__ x, const float* __restrict__ W1,
                           float* __restrict__ PQ){
    int i = blockIdx.x*256 + threadIdx.x;      // over BN_*64
    int c = i & 63; int p = i >> 6;
    int b = p >> 12, n = p & (NNN-1);
    const float* xb = x + (size_t)b*3*NNN + n;
    float x0 = xb[0], x1 = xb[NNN], x2 = xb[2*NNN];
    const float* w = W1 + c*6;
    float pv = x0*w[0] + x1*w[1] + x2*w[2];
    float qv = x0*(w[3]-w[0]) + x1*(w[4]-w[1]) + x2*(w[5]-w[2]);
    PQ[(size_t)p*128 + c]      = pv;
    PQ[(size_t)p*128 + 64 + c] = qv;
}

// ---------------- weight prep: W (64x128) -> Wpq (128x64) ------------------
__global__ void wprep_kernel(const float* __restrict__ W, float* __restrict__ Wpq){
    int i = blockIdx.x*256 + threadIdx.x;      // 8192
    int c = i & 63; int r = i >> 6;
    float v;
    if (r < 64) v = W[r*128 + c];
    else { int o = r - 64; v = W[o*128 + 64 + c] - W[o*128 + c]; }
    Wpq[r*64 + c] = v;
}

// ---------------- fused: edge build + BN/lrelu + 64x64 GEMM + BN/lrelu + max_k
__global__ void __launch_bounds__(256) fused_edge(
        const float* __restrict__ PQ,
        const float* __restrict__ sa, const float* __restrict__ ba,
        const float* __restrict__ W2,
        const float* __restrict__ sb, const float* __restrict__ bb,
        const int* __restrict__ idx, float* __restrict__ xout, int ostride)
{
    __shared__ float As[40][68];
    __shared__ float Ws[64][68];
    __shared__ float red[8][64];
    __shared__ float qrow[64], sav[64], bav[64];
    __shared__ int js[40];
    int p = blockIdx.x; int b = p >> 12;
    int tid = threadIdx.x;
    for (int i = tid; i < 4096; i += 256) Ws[i>>6][i&63] = W2[i];
    if (tid < 64){
        qrow[tid] = PQ[(size_t)p*128 + 64 + tid];
        sav[tid] = sa[tid]; bav[tid] = ba[tid];
    }
    if (tid < 40) js[tid] = idx[(size_t)p*NKK + tid];
    __syncthreads();
    int base = b << 12;
    for (int e = tid; e < 2560; e += 256){
        int k = e >> 6, c = e & 63;
        float v = PQ[((size_t)(base + js[k]))*128 + c] + qrow[c];
        v = sav[c]*v + bav[c];
        As[k][c] = v > 0.f ? v : 0.2f*v;
    }
    __syncthreads();
    int w = tid >> 5, tx = tid & 31;
    float acc[5][2];
    #pragma unroll
    for (int i=0;i<5;i++){ acc[i][0]=0.f; acc[i][1]=0.f; }
    #pragma unroll
    for (int c4=0;c4<16;c4++){
        float4 w0 = *(const float4*)&Ws[tx][c4*4];
        float4 w1 = *(const float4*)&Ws[tx+32][c4*4];
        #pragma unroll
        for (int i=0;i<5;i++){
            int k = w + 8*i;
            float4 a = *(const float4*)&As[k][c4*4];
            acc[i][0] += a.x*w0.x + a.y*w0.y + a.z*w0.z + a.w*w0.w;
            acc[i][1] += a.x*w1.x + a.y*w1.y + a.z*w1.z + a.w*w1.w;
        }
    }
    float s0 = sb[tx],    bb0 = bb[tx];
    float s1 = sb[tx+32], bb1 = bb[tx+32];
    float m0 = -FLT_MAX, m1 = -FLT_MAX;
    #pragma unroll
    for (int i=0;i<5;i++){
        float z0 = s0*acc[i][0] + bb0; z0 = z0>0.f? z0 : 0.2f*z0;
        float z1 = s1*acc[i][1] + bb1; z1 = z1>0.f? z1 : 0.2f*z1;
        m0 = fmaxf(m0, z0); m1 = fmaxf(m1, z1);
    }
    red[w][tx] = m0; red[w][tx+32] = m1;
    __syncthreads();
    if (tid < 64){
        float m = red[0][tid];
        #pragma unroll
        for (int r=1;r<8;r++) m = fmaxf(m, red[r][tid]);
        xout[(size_t)p*ostride + tid] = m;
    }
}

// ---------------- stage 3: gather + BN/lrelu + max_k (no second GEMM) ------
__global__ void maxgather_kernel(const float* __restrict__ PQ,
                                 const float* __restrict__ s, const float* __restrict__ bias,
                                 const int* __restrict__ idx,
                                 float* __restrict__ xout, int ostride){
    int i = blockIdx.x*256 + threadIdx.x;   // BN_*64
    int o = i & 63, p = i >> 6; int b = p >> 12;
    float qv = PQ[(size_t)p*128 + 64 + o];
    float sc = s[o], bv = bias[o];
    const int* ip = idx + (size_t)p*NKK;
    size_t base = (size_t)(b << 12)*128;
    float m = -FLT_MAX;
    #pragma unroll 8
    for (int k=0;k<NKK;k++){
        float v = PQ[base + (size_t)ip[k]*128 + o] + qv;
        v = sc*v + bv;
        v = v>0.f? v : 0.2f*v;
        m = fmaxf(m, v);
    }
    xout[(size_t)p*ostride + o] = m;
}

__global__ void init_gmax(unsigned* g){
    int i = blockIdx.x*256 + threadIdx.x;
    if (i < NBB*1024) g[i] = 0u;
}

// ---------------- Gb[b][o] = sum_c g[b,c] * W7[o,c]  (c < 1024) ------------
__global__ void gb_kernel(const unsigned* __restrict__ gmax, const float* __restrict__ W7,
                          float* __restrict__ Gb){
    int i = blockIdx.x*256 + threadIdx.x;   // 2048
    int o = i & 511; int b = i >> 9;
    const unsigned* gm = gmax + b*1024;
    const float* w = W7 + (size_t)o*1216;
    float a0=0.f,a1=0.f,a2=0.f,a3=0.f;
    for (int c=0;c<1024;c+=4){
        a0 += dec_f(gm[c+0])*w[c+0];
        a1 += dec_f(gm[c+1])*w[c+1];
        a2 += dec_f(gm[c+2])*w[c+2];
        a3 += dec_f(gm[c+3])*w[c+3];
    }
    Gb[(size_t)b*512 + o] = (a0+a1)+(a2+a3);
}

// ---------------- 128x128x8 fp32 GEMM, 8x8 split microtile ------------------
// modes: 0 = store C (Nd must be multiple of 4 via full tiles; used with Nd%128==0)
//        1 = transpose store out[(b*Nd+n)*4096 + (m&4095)], scalar, n<Nd guard
//        2 = gmax atomic reduce over rows (per-batch), no C store
__global__ void __launch_bounds__(256,2) gemm128(
        const float* __restrict__ A, int lda,
        const float* __restrict__ W, int ldw,
        const float* __restrict__ s, const float* __restrict__ bias,
        const float* __restrict__ Gb,
        float* __restrict__ C, int ldc, unsigned* gmax,
        int Kd, int Nd, float leak, int mode)
{
    __shared__ float As[8][132];
    __shared__ float Ws[8][132];
    int m0 = blockIdx.x*128, n0 = blockIdx.y*128;
    int tid = threadIdx.x;
    int hr = tid >> 1;
    int kq = (tid & 1)*4;
    const float* Ap = A + (size_t)(m0 + hr)*lda + kq;
    bool wval = (n0 + hr) < Nd;
    const float* Wp = W + (size_t)(n0 + (wval ? hr : 0))*ldw + kq;
    int tx = tid & 15, ty = tid >> 4;
    float acc[8][8];
    #pragma unroll
    for (int i=0;i<8;i++)
        #pragma unroll
        for (int j=0;j<8;j++) acc[i][j]=0.f;

    for (int k0 = 0; k0 < Kd; k0 += 8){
        float4 a4 = *(const float4*)(Ap + k0);
        float4 w4 = wval ? *(const float4*)(Wp + k0) : make_float4(0.f,0.f,0.f,0.f);
        As[kq+0][hr]=a4.x; As[kq+1][hr]=a4.y; As[kq+2][hr]=a4.z; As[kq+3][hr]=a4.w;
        Ws[kq+0][hr]=w4.x; Ws[kq+1][hr]=w4.y; Ws[kq+2][hr]=w4.z; Ws[kq+3][hr]=w4.w;
        __syncthreads();
        #pragma unroll
        for (int k=0;k<8;k++){
            float4 a0 = *(const float4*)&As[k][ty*4];
            float4 a1 = *(const float4*)&As[k][64+ty*4];
            float4 w0 = *(const float4*)&Ws[k][tx*4];
            float4 w1 = *(const float4*)&Ws[k][64+tx*4];
            float ar[8] = {a0.x,a0.y,a0.z,a0.w,a1.x,a1.y,a1.z,a1.w};
            float wr[8] = {w0.x,w0.y,w0.z,w0.w,w1.x,w1.y,w1.z,w1.w};
            #pragma unroll
            for (int i=0;i<8;i++)
                #pragma unroll
                for (int j=0;j<8;j++) acc[i][j] += ar[i]*wr[j];
        }
        __syncthreads();
    }

    int b = m0 >> 12;
    if (mode == 0){
        #pragma unroll
        for (int i=0;i<8;i++){
            int m = m0 + (i<4 ? ty*4+i : 64 + ty*4 + (i-4));
            #pragma unroll
            for (int h=0; h<2; h++){
                int n = n0 + (h ? 64 + tx*4 : tx*4);
                float z[4];
                #pragma unroll
                for (int j=0;j<4;j++) z[j] = acc[i][h*4+j];
                if (Gb){
                    float4 g4 = *(const float4*)&Gb[(size_t)b*Nd + n];
                    z[0]+=g4.x; z[1]+=g4.y; z[2]+=g4.z; z[3]+=g4.w;
                }
                if (s){
                    float4 s4 = *(const float4*)&s[n];
                    float4 b4 = *(const float4*)&bias[n];
                    z[0]=s4.x*z[0]+b4.x; z[1]=s4.y*z[1]+b4.y;
                    z[2]=s4.z*z[2]+b4.z; z[3]=s4.w*z[3]+b4.w;
                } else if (bias){
                    float4 b4 = *(const float4*)&bias[n];
                    z[0]+=b4.x; z[1]+=b4.y; z[2]+=b4.z; z[3]+=b4.w;
                }
                float4 o4;
                o4.x = z[0]>0.f? z[0] : leak*z[0];
                o4.y = z[1]>0.f? z[1] : leak*z[1];
                o4.z = z[2]>0.f? z[2] : leak*z[2];
                o4.w = z[3]>0.f? z[3] : leak*z[3];
                *(float4*)&C[(size_t)m*ldc + n] = o4;
            }
        }
    } else if (mode == 1){
        #pragma unroll
        for (int i=0;i<8;i++){
            int m = m0 + (i<4 ? ty*4+i : 64 + ty*4 + (i-4));
            int bb_ = m >> 12, nn = m & (NNN-1);
            #pragma unroll
            for (int j=0;j<8;j++){
                int n = n0 + (j<4 ? tx*4+j : 64 + tx*4 + (j-4));
                if (n < Nd){
                    float z = acc[i][j] + (bias ? bias[n] : 0.f);
                    C[((size_t)bb_*Nd + n)*NNN + nn] = z;
                }
            }
        }
    } else {
        // mode 2: BN + lrelu, max over the 128 rows of this tile, atomic to gmax
        float cm[8];
        #pragma unroll
        for (int j=0;j<8;j++){
            int n = n0 + (j<4 ? tx*4+j : 64 + tx*4 + (j-4));
            float sn = s[n], bn = bias[n];
            float m = -FLT_MAX;
            #pragma unroll
            for (int i=0;i<8;i++){
                float z = sn*acc[i][j] + bn;
                z = z>0.f? z : leak*z;
                m = fmaxf(m, z);
            }
            cm[j] = m;
        }
        float (*red)[128] = (float(*)[128])&As[0][0];   // 16x128 = 8KB, fits As+Ws
        #pragma unroll
        for (int j=0;j<8;j++){
            int col = (j<4 ? tx*4+j : 64 + tx*4 + (j-4));
            red[ty][col] = (ty==0) ? cm[j] : cm[j];
        }
        // need all 16 ty rows: red[ty][col]
        __syncthreads();
        if (tid < 128){
            float m = red[0][tid];
            #pragma unroll
            for (int r=1;r<16;r++) m = fmaxf(m, red[r][tid]);
            atomicMax(&gmax[b*1024 + n0 + tid], enc_f(m));
        }
    }
}

// ---------------------------------------------------------------------------
extern "C" void kernel_launch(void* const* d_in, const int* in_sizes, int n_in,
                              void* d_out, int out_size){
    const float* x  = (const float*)d_in[0];
    const float* W1 = (const float*)d_in[1];
    const float* s1 = (const float*)d_in[2];
    const float* b1 = (const float*)d_in[3];
    const float* W2 = (const float*)d_in[4];
    const float* s2 = (const float*)d_in[5];
    const float* b2 = (const float*)d_in[6];
    const float* W3 = (const float*)d_in[7];
    const float* s3 = (const float*)d_in[8];
    const float* b3 = (const float*)d_in[9];
    const float* W4 = (const float*)d_in[10];
    const float* s4 = (const float*)d_in[11];
    const float* b4 = (const float*)d_in[12];
    const float* W5 = (const float*)d_in[13];
    const float* s5 = (const float*)d_in[14];
    const float* b5 = (const float*)d_in[15];
    const float* W6 = (const float*)d_in[16];
    const float* s6 = (const float*)d_in[17];
    const float* b6 = (const float*)d_in[18];
    const float* W7 = (const float*)d_in[19];
    const float* s7 = (const float*)d_in[20];
    const float* b7 = (const float*)d_in[21];
    const float* W8 = (const float*)d_in[22];
    const float* s8 = (const float*)d_in[23];
    const float* b8 = (const float*)d_in[24];
    const float* W9 = (const float*)d_in[25];
    const float* b9 = (const float*)d_in[26];
    float* out = (float*)d_out;

    float *nrm,*xcat,*PQ,*h7,*h8,*Wpq,*Gb; int* idx; unsigned* gmax;
    cudaGetSymbolAddress((void**)&nrm,  d_nrm);
    cudaGetSymbolAddress((void**)&idx,  d_idx);
    cudaGetSymbolAddress((void**)&xcat, d_xcat);
    cudaGetSymbolAddress((void**)&PQ,   d_PQ);
    cudaGetSymbolAddress((void**)&h7,   d_h7);
    cudaGetSymbolAddress((void**)&h8,   d_h8);
    cudaGetSymbolAddress((void**)&Wpq,  d_Wpq);
    cudaGetSymbolAddress((void**)&gmax, d_gmax);
    cudaGetSymbolAddress((void**)&Gb,   d_Gb);

    const float LK = 0.2f;

    nrm_kernel<<<64,256>>>(x, nrm);
    knn_kernel<<<BN_,256>>>(x, nrm, idx);

    // stage 1: P/Q from coords, fused edge conv (conv1+conv2) + max_k -> x1
    pq1_kernel<<<4096,256>>>(x, W1, PQ);
    fused_edge<<<BN_,256>>>(PQ, s1, b1, W2, s2, b2, idx, xcat + 0, 192);

    // stage 2: P/Q = x1 * Wpq3, fused edge conv (conv3+conv4) + max_k -> x2
    wprep_kernel<<<32,256>>>(W3, Wpq);
    gemm128<<<dim3(128,1),256>>>(xcat, 192, Wpq, 64, nullptr, nullptr, nullptr,
                                 PQ, 128, nullptr, 64, 128, 1.f, 0);
    fused_edge<<<BN_,256>>>(PQ, s3, b3, W4, s4, b4, idx, xcat + 64, 192);

    // stage 3: P/Q = x2 * Wpq5, gather + lrelu + max_k -> x3
    wprep_kernel<<<32,256>>>(W5, Wpq);
    gemm128<<<dim3(128,1),256>>>(xcat + 64, 192, Wpq, 64, nullptr, nullptr, nullptr,
                                 PQ, 128, nullptr, 64, 128, 1.f, 0);
    maxgather_kernel<<<4096,256>>>(PQ, s5, b5, idx, xcat + 128, 192);

    // conv6 (192 -> 1024) with fused max over N (atomic)
    init_gmax<<<16,256>>>(gmax);
    gemm128<<<dim3(128,8),256>>>(xcat, 192, W6, 192, s6, b6, nullptr,
                                 nullptr, 0, gmax, 192, 1024, LK, 2);

    // per-batch bias from g through W7's first 1024 input channels
    gb_kernel<<<8,256>>>(gmax, W7, Gb);

    // conv7: xcat (192) through W7[:,1024:] + Gb  -> h7 (512)
    gemm128<<<dim3(128,4),256>>>(xcat, 192, W7 + 1024, 1216, s7, b7, Gb,
                                 h7, 512, nullptr, 192, 512, LK, 0);
    // conv8: 512 -> 256
    gemm128<<<dim3(128,2),256>>>(h7, 512, W8, 512, s8, b8, nullptr,
                                 h8, 256, nullptr, 512, 256, LK, 0);
    // conv9: 256 -> 63, + bias, transposed store
    gemm128<<<dim3(128,1),256>>>(h8, 256, W9, 256, nullptr, b9, nullptr,
                                 out, 63, nullptr, 256, 63, 1.f, 1);
}

// round 3
// speedup vs baseline: 2.6327x; 1.2778x over previous
#include <cuda_runtime.h>
#include <float.h>
#include <stdint.h>

#define NBB 4
#define NNN 4096
#define NKK 40
#define BN_ (NBB*NNN)            // 16384
#define BNK (BN_*NKK)            // 655360

// ---------------- static scratch ----------------
__device__ float    d_nrm[BN_];
__device__ int      d_idx[BNK];
__device__ float    d_xcat[(size_t)BN_*192];   // [x1|x2|x3] per point
__device__ float    d_PQ[(size_t)BN_*128];     // P (0..63) | Q (64..127)
__device__ float    d_h7[(size_t)BN_*512];
__device__ float    d_h8[(size_t)BN_*256];
__device__ float    d_Wpq[128*64];
__device__ unsigned d_gmax[NBB*1024];
__device__ float    d_Gb[NBB*512];

__device__ __forceinline__ unsigned enc_f(float f){
    unsigned u = __float_as_uint(f);
    return (u & 0x80000000u) ? ~u : (u | 0x80000000u);
}
__device__ __forceinline__ float dec_f(unsigned k){
    unsigned u = (k & 0x80000000u) ? (k & 0x7FFFFFFFu) : ~k;
    return __uint_as_float(u);
}
__device__ __forceinline__ uint32_t f2tf(float f){
    uint32_t r; asm("cvt.rna.tf32.f32 %0, %1;" : "=r"(r) : "f"(f)); return r;
}
__device__ __forceinline__ void mma_tf32(float4 &c, const uint32_t* a, const uint32_t* b){
    asm volatile("mma.sync.aligned.m16n8k8.row.col.f32.tf32.tf32.f32 "
        "{%0,%1,%2,%3}, {%4,%5,%6,%7}, {%8,%9}, {%0,%1,%2,%3};"
        : "+f"(c.x), "+f"(c.y), "+f"(c.z), "+f"(c.w)
        : "r"(a[0]), "r"(a[1]), "r"(a[2]), "r"(a[3]), "r"(b[0]), "r"(b[1]));
}

// ---------------- squared norms ----------------
__global__ void nrm_kernel(const float* __restrict__ x, float* __restrict__ nrm){
    int i = blockIdx.x*256 + threadIdx.x;
    if (i >= BN_) return;
    int b = i >> 12, n = i & (NNN-1);
    const float* xb = x + (size_t)b*3*NNN;
    float a = xb[n], c = xb[NNN+n], d = xb[2*NNN+n];
    nrm[i] = a*a + c*c + d*d;
}

// ---------------- kNN: one block per query point ----------------
__global__ void __launch_bounds__(256) knn_kernel(const float* __restrict__ x,
                                                  const float* __restrict__ nrm,
                                                  int* __restrict__ idxo){
    __shared__ float pd[NNN];
    __shared__ float segv[256];
    __shared__ int   segp[256];
    __shared__ float wv[8];
    __shared__ int   wp[8];
    __shared__ int   sh_win;
    int blk = blockIdx.x;
    int b = blk >> 12;
    int n = blk & (NNN-1);
    int tid = threadIdx.x;
    const float* xb = x + (size_t)b*3*NNN;
    const float* nb = nrm + b*NNN;
    float qx = xb[n], qy = xb[NNN+n], qz = xb[2*NNN+n];
    float qn = nb[n];
    for (int i = tid; i < NNN; i += 256){
        float d = 2.f*(qx*xb[i] + qy*xb[NNN+i] + qz*xb[2*NNN+i]) - qn - nb[i];
        pd[i] = d;
    }
    __syncthreads();
    {
        int base = tid*16;
        float v = pd[base]; int p = base;
        #pragma unroll
        for (int i=1;i<16;i++){ float t = pd[base+i]; if (t > v){ v=t; p=base+i; } }
        segv[tid]=v; segp[tid]=p;
    }
    __syncthreads();
    int* out = idxo + (size_t)blk*NKK;
    for (int kk=0; kk<NKK; kk++){
        float v = segv[tid]; int p = segp[tid];
        #pragma unroll
        for (int off=16; off>0; off>>=1){
            float ov = __shfl_down_sync(0xffffffffu, v, off);
            int   op = __shfl_down_sync(0xffffffffu, p, off);
            if (ov > v || (ov == v && op < p)){ v=ov; p=op; }
        }
        if ((tid & 31) == 0){ wv[tid>>5]=v; wp[tid>>5]=p; }
        __syncthreads();
        if (tid == 0){
            float bv = wv[0]; int bp = wp[0];
            #pragma unroll
            for (int w=1; w<8; w++){
                if (wv[w] > bv || (wv[w]==bv && wp[w]<bp)){ bv=wv[w]; bp=wp[w]; }
            }
            sh_win = bp;
            out[kk] = bp;
        }
        __syncthreads();
        int w = sh_win;
        if (tid == (w >> 4)){
            pd[w] = -FLT_MAX;
            int base = tid*16;
            float v2 = pd[base]; int p2 = base;
            #pragma unroll
            for (int i=1;i<16;i++){ float t=pd[base+i]; if (t>v2){v2=t;p2=base+i;} }
            segv[tid]=v2; segp[tid]=p2;
        }
        __syncthreads();
    }
}

// ---------------- P/Q from coords (stage 1) --------------------------------
__global__ void pq1_kernel(const float* __restrict__ x, const float* __restrict__ W1,
                           float* __restrict__ PQ){
    int i = blockIdx.x*256 + threadIdx.x;      // over BN_*64
    int c = i & 63; int p = i >> 6;
    int b = p >> 12, n = p & (NNN-1);
    const float* xb = x + (size_t)b*3*NNN + n;
    float x0 = xb[0], x1 = xb[NNN], x2 = xb[2*NNN];
    const float* w = W1 + c*6;
    float pv = x0*w[0] + x1*w[1] + x2*w[2];
    float qv = x0*(w[3]-w[0]) + x1*(w[4]-w[1]) + x2*(w[5]-w[2]);
    PQ[(size_t)p*128 + c]      = pv;
    PQ[(size_t)p*128 + 64 + c] = qv;
}

// ---------------- weight prep: W (64x128) -> Wpq (128x64) ------------------
__global__ void wprep_kernel(const float* __restrict__ W, float* __restrict__ Wpq){
    int i = blockIdx.x*256 + threadIdx.x;      // 8192
    int c = i & 63; int r = i >> 6;
    float v;
    if (r < 64) v = W[r*128 + c];
    else { int o = r - 64; v = W[o*128 + 64 + c] - W[o*128 + c]; }
    Wpq[r*64 + c] = v;
}

// ---------------- fused edge conv via tf32 mma ------------------------------
// per point: build A[40][64] (gather+BN+lrelu, pad to 48), C = A * W2^T,
// BN+lrelu, max over 40 rows -> xout[64]
__global__ void __launch_bounds__(256) fused_edge_tc(
        const float* __restrict__ PQ,
        const float* __restrict__ sa, const float* __restrict__ ba,
        const float* __restrict__ W2,
        const float* __restrict__ sb, const float* __restrict__ bb,
        const int* __restrict__ idx, float* __restrict__ xout, int ostride)
{
    __shared__ uint32_t As[48][68];
    __shared__ uint32_t Ws[64][68];
    __shared__ float qrow[64], sav[64], bav[64];
    __shared__ int js[40];
    int p = blockIdx.x; int b = p >> 12;
    int tid = threadIdx.x;
    int w = tid >> 5, lane = tid & 31;
    int gid = lane >> 2, tig = lane & 3;

    for (int i = tid; i < 4096; i += 256) Ws[i>>6][i&63] = f2tf(W2[i]);
    if (tid < 64){
        qrow[tid] = PQ[(size_t)p*128 + 64 + tid];
        sav[tid] = sa[tid]; bav[tid] = ba[tid];
    }
    if (tid < 40) js[tid] = idx[(size_t)p*NKK + tid];
    __syncthreads();
    int base = b << 12;
    for (int e = tid; e < 3072; e += 256){
        int k = e >> 6, c = e & 63;
        float v = 0.f;
        if (k < 40){
            v = PQ[((size_t)(base + js[k]))*128 + c] + qrow[c];
            v = sav[c]*v + bav[c];
            v = v > 0.f ? v : 0.2f*v;
        }
        As[k][c] = f2tf(v);
    }
    __syncthreads();

    float4 acc[3];
    #pragma unroll
    for (int mt=0;mt<3;mt++) acc[mt] = make_float4(0.f,0.f,0.f,0.f);
    #pragma unroll
    for (int k0=0;k0<64;k0+=8){
        uint32_t bf[2];
        bf[0] = Ws[w*8+gid][k0+tig];
        bf[1] = Ws[w*8+gid][k0+tig+4];
        #pragma unroll
        for (int mt=0;mt<3;mt++){
            uint32_t af[4];
            int r = mt*16;
            af[0] = As[r+gid  ][k0+tig];
            af[1] = As[r+gid+8][k0+tig];
            af[2] = As[r+gid  ][k0+tig+4];
            af[3] = As[r+gid+8][k0+tig+4];
            mma_tf32(acc[mt], af, bf);
        }
    }
    // epilogue: BN + lrelu per element, max over valid rows (0..39)
    int c0 = w*8 + 2*tig;
    float s0 = sb[c0], o0 = bb[c0], s1 = sb[c0+1], o1 = bb[c0+1];
    float mx = -FLT_MAX, my = -FLT_MAX;
    #pragma unroll
    for (int mt=0;mt<3;mt++){
        float z;
        z = s0*acc[mt].x + o0; z = z>0.f? z : 0.2f*z; mx = fmaxf(mx, z);
        z = s1*acc[mt].y + o1; z = z>0.f? z : 0.2f*z; my = fmaxf(my, z);
        if (mt < 2){
            z = s0*acc[mt].z + o0; z = z>0.f? z : 0.2f*z; mx = fmaxf(mx, z);
            z = s1*acc[mt].w + o1; z = z>0.f? z : 0.2f*z; my = fmaxf(my, z);
        }
    }
    #pragma unroll
    for (int off=4; off<32; off<<=1){
        mx = fmaxf(mx, __shfl_xor_sync(0xffffffffu, mx, off));
        my = fmaxf(my, __shfl_xor_sync(0xffffffffu, my, off));
    }
    if (gid == 0){
        xout[(size_t)p*ostride + c0]     = mx;
        xout[(size_t)p*ostride + c0 + 1] = my;
    }
}

// ---------------- stage 3: gather + BN/lrelu + max_k -----------------------
__global__ void maxgather_kernel(const float* __restrict__ PQ,
                                 const float* __restrict__ s, const float* __restrict__ bias,
                                 const int* __restrict__ idx,
                                 float* __restrict__ xout, int ostride){
    int i = blockIdx.x*256 + threadIdx.x;   // BN_*64
    int o = i & 63, p = i >> 6; int b = p >> 12;
    float qv = PQ[(size_t)p*128 + 64 + o];
    float sc = s[o], bv = bias[o];
    const int* ip = idx + (size_t)p*NKK;
    size_t base = (size_t)(b << 12)*128;
    float m = -FLT_MAX;
    #pragma unroll 8
    for (int k=0;k<NKK;k++){
        float v = PQ[base + (size_t)ip[k]*128 + o] + qv;
        v = sc*v + bv;
        v = v>0.f? v : 0.2f*v;
        m = fmaxf(m, v);
    }
    xout[(size_t)p*ostride + o] = m;
}

__global__ void init_gmax(unsigned* g){
    int i = blockIdx.x*256 + threadIdx.x;
    if (i < NBB*1024) g[i] = 0u;
}

// ---------------- Gb[b][o] = sum_c g[b,c] * W7[o,c]  (c < 1024) ------------
__global__ void gb_kernel(const unsigned* __restrict__ gmax, const float* __restrict__ W7,
                          float* __restrict__ Gb){
    int i = blockIdx.x*256 + threadIdx.x;   // 2048
    int o = i & 511; int b = i >> 9;
    const unsigned* gm = gmax + b*1024;
    const float* w = W7 + (size_t)o*1216;
    float a0=0.f,a1=0.f,a2=0.f,a3=0.f;
    for (int c=0;c<1024;c+=4){
        a0 += dec_f(gm[c+0])*w[c+0];
        a1 += dec_f(gm[c+1])*w[c+1];
        a2 += dec_f(gm[c+2])*w[c+2];
        a3 += dec_f(gm[c+3])*w[c+3];
    }
    Gb[(size_t)b*512 + o] = (a0+a1)+(a2+a3);
}

// ---------------- tf32 tensor-core GEMM, 128x128 tile ----------------------
// C[m,n] = act( s[n]*(sum_k A[m,k]*W[n,k] + Gb[b,n]) + bias[n] )
// mode 0: store C.  mode 2: BN+lrelu then atomicMax over rows into gmax.
// Requires: Kd % 16 == 0, Nd % 128 == 0, M % 128 == 0.
__global__ void __launch_bounds__(256,2) gemm_tc(
        const float* __restrict__ A, int lda,
        const float* __restrict__ W, int ldw,
        const float* __restrict__ s, const float* __restrict__ bias,
        const float* __restrict__ Gb,
        float* __restrict__ C, int ldc, unsigned* gmax,
        int Kd, int Nd, float leak, int mode)
{
    __shared__ uint32_t As[128][20];
    __shared__ uint32_t Ws[128][20];
    int m0 = blockIdx.x*128, n0 = blockIdx.y*128;
    int tid = threadIdx.x, lane = tid & 31, w = tid >> 5;
    int gid = lane >> 2, tig = lane & 3;
    int wm = (w >> 2)*64, wn = (w & 3)*32;
    float4 acc[4][4];
    #pragma unroll
    for (int mt=0;mt<4;mt++)
        #pragma unroll
        for (int nt=0;nt<4;nt++) acc[mt][nt] = make_float4(0.f,0.f,0.f,0.f);

    int lr = tid >> 1, lq = (tid & 1)*8;
    const float* Ap = A + (size_t)(m0+lr)*lda + lq;
    const float* Wp = W + (size_t)(n0+lr)*ldw + lq;

    for (int k0 = 0; k0 < Kd; k0 += 16){
        float4 a0 = *(const float4*)(Ap + k0);
        float4 a1 = *(const float4*)(Ap + k0 + 4);
        float4 w0 = *(const float4*)(Wp + k0);
        float4 w1 = *(const float4*)(Wp + k0 + 4);
        uint4 ua0 = {f2tf(a0.x),f2tf(a0.y),f2tf(a0.z),f2tf(a0.w)};
        uint4 ua1 = {f2tf(a1.x),f2tf(a1.y),f2tf(a1.z),f2tf(a1.w)};
        uint4 uw0 = {f2tf(w0.x),f2tf(w0.y),f2tf(w0.z),f2tf(w0.w)};
        uint4 uw1 = {f2tf(w1.x),f2tf(w1.y),f2tf(w1.z),f2tf(w1.w)};
        *(uint4*)&As[lr][lq]   = ua0;
        *(uint4*)&As[lr][lq+4] = ua1;
        *(uint4*)&Ws[lr][lq]   = uw0;
        *(uint4*)&Ws[lr][lq+4] = uw1;
        __syncthreads();
        #pragma unroll
        for (int ks=0; ks<16; ks+=8){
            uint32_t bf[4][2];
            #pragma unroll
            for (int nt=0;nt<4;nt++){
                int n = wn + nt*8 + gid;
                bf[nt][0] = Ws[n][ks+tig];
                bf[nt][1] = Ws[n][ks+tig+4];
            }
            #pragma unroll
            for (int mt=0;mt<4;mt++){
                uint32_t af[4];
                int r = wm + mt*16;
                af[0] = As[r+gid  ][ks+tig];
                af[1] = As[r+gid+8][ks+tig];
                af[2] = As[r+gid  ][ks+tig+4];
                af[3] = As[r+gid+8][ks+tig+4];
                #pragma unroll
                for (int nt=0;nt<4;nt++) mma_tf32(acc[mt][nt], af, bf[nt]);
            }
        }
        __syncthreads();
    }

    int b = m0 >> 12;
    if (mode == 0){
        #pragma unroll
        for (int mt=0;mt<4;mt++){
            int r0 = m0 + wm + mt*16 + gid;
            #pragma unroll
            for (int nt=0;nt<4;nt++){
                int cg = n0 + wn + nt*8 + 2*tig;
                float gx = 0.f, gy = 0.f;
                if (Gb){ gx = Gb[(size_t)b*Nd + cg]; gy = Gb[(size_t)b*Nd + cg + 1]; }
                float sx=1.f, sy=1.f, bx=0.f, by=0.f;
                if (s){ sx=s[cg]; sy=s[cg+1]; bx=bias[cg]; by=bias[cg+1]; }
                else if (bias){ bx=bias[cg]; by=bias[cg+1]; }
                float4 a = acc[mt][nt];
                float z0 = sx*(a.x+gx)+bx; z0 = z0>0.f? z0 : leak*z0;
                float z1 = sy*(a.y+gy)+by; z1 = z1>0.f? z1 : leak*z1;
                float z2 = sx*(a.z+gx)+bx; z2 = z2>0.f? z2 : leak*z2;
                float z3 = sy*(a.w+gy)+by; z3 = z3>0.f? z3 : leak*z3;
                *(float2*)&C[(size_t)r0*ldc + cg]     = make_float2(z0,z1);
                *(float2*)&C[(size_t)(r0+8)*ldc + cg] = make_float2(z2,z3);
            }
        }
    } else {
        #pragma unroll
        for (int nt=0;nt<4;nt++){
            int cg = n0 + wn + nt*8 + 2*tig;
            float sx=s[cg], bx=bias[cg], sy=s[cg+1], by=bias[cg+1];
            float mx=-FLT_MAX, my=-FLT_MAX;
            #pragma unroll
            for (int mt=0;mt<4;mt++){
                float4 a = acc[mt][nt];
                float z;
                z = sx*a.x+bx; z = z>0.f? z : leak*z; mx = fmaxf(mx,z);
                z = sx*a.z+bx; z = z>0.f? z : leak*z; mx = fmaxf(mx,z);
                z = sy*a.y+by; z = z>0.f? z : leak*z; my = fmaxf(my,z);
                z = sy*a.w+by; z = z>0.f? z : leak*z; my = fmaxf(my,z);
            }
            #pragma unroll
            for (int off=4; off<32; off<<=1){
                mx = fmaxf(mx, __shfl_xor_sync(0xffffffffu, mx, off));
                my = fmaxf(my, __shfl_xor_sync(0xffffffffu, my, off));
            }
            if (gid == 0){
                atomicMax(&gmax[b*1024 + cg],     enc_f(mx));
                atomicMax(&gmax[b*1024 + cg + 1], enc_f(my));
            }
        }
    }
}

// ---------------- small fp32 GEMM kept for conv9 (mode1 transposed store) ---
__global__ void __launch_bounds__(256,2) gemm128(
        const float* __restrict__ A, int lda,
        const float* __restrict__ W, int ldw,
        const float* __restrict__ bias,
        float* __restrict__ C, int Kd, int Nd)
{
    __shared__ float As[8][132];
    __shared__ float Ws[8][132];
    int m0 = blockIdx.x*128, n0 = blockIdx.y*128;
    int tid = threadIdx.x;
    int hr = tid >> 1;
    int kq = (tid & 1)*4;
    const float* Ap = A + (size_t)(m0 + hr)*lda + kq;
    bool wval = (n0 + hr) < Nd;
    const float* Wp = W + (size_t)(n0 + (wval ? hr : 0))*ldw + kq;
    int tx = tid & 15, ty = tid >> 4;
    float acc[8][8];
    #pragma unroll
    for (int i=0;i<8;i++)
        #pragma unroll
        for (int j=0;j<8;j++) acc[i][j]=0.f;

    for (int k0 = 0; k0 < Kd; k0 += 8){
        float4 a4 = *(const float4*)(Ap + k0);
        float4 w4 = wval ? *(const float4*)(Wp + k0) : make_float4(0.f,0.f,0.f,0.f);
        As[kq+0][hr]=a4.x; As[kq+1][hr]=a4.y; As[kq+2][hr]=a4.z; As[kq+3][hr]=a4.w;
        Ws[kq+0][hr]=w4.x; Ws[kq+1][hr]=w4.y; Ws[kq+2][hr]=w4.z; Ws[kq+3][hr]=w4.w;
        __syncthreads();
        #pragma unroll
        for (int k=0;k<8;k++){
            float4 a0 = *(const float4*)&As[k][ty*4];
            float4 a1 = *(const float4*)&As[k][64+ty*4];
            float4 w0 = *(const float4*)&Ws[k][tx*4];
            float4 w1 = *(const float4*)&Ws[k][64+tx*4];
            float ar[8] = {a0.x,a0.y,a0.z,a0.w,a1.x,a1.y,a1.z,a1.w};
            float wr[8] = {w0.x,w0.y,w0.z,w0.w,w1.x,w1.y,w1.z,w1.w};
            #pragma unroll
            for (int i=0;i<8;i++)
                #pragma unroll
                for (int j=0;j<8;j++) acc[i][j] += ar[i]*wr[j];
        }
        __syncthreads();
    }
    #pragma unroll
    for (int i=0;i<8;i++){
        int m = m0 + (i<4 ? ty*4+i : 64 + ty*4 + (i-4));
        int bb_ = m >> 12, nn = m & (NNN-1);
        #pragma unroll
        for (int j=0;j<8;j++){
            int n = n0 + (j<4 ? tx*4+j : 64 + tx*4 + (j-4));
            if (n < Nd){
                float z = acc[i][j] + (bias ? bias[n] : 0.f);
                C[((size_t)bb_*Nd + n)*NNN + nn] = z;
            }
        }
    }
}

// ---------------------------------------------------------------------------
extern "C" void kernel_launch(void* const* d_in, const int* in_sizes, int n_in,
                              void* d_out, int out_size){
    const float* x  = (const float*)d_in[0];
    const float* W1 = (const float*)d_in[1];
    const float* s1 = (const float*)d_in[2];
    const float* b1 = (const float*)d_in[3];
    const float* W2 = (const float*)d_in[4];
    const float* s2 = (const float*)d_in[5];
    const float* b2 = (const float*)d_in[6];
    const float* W3 = (const float*)d_in[7];
    const float* s3 = (const float*)d_in[8];
    const float* b3 = (const float*)d_in[9];
    const float* W4 = (const float*)d_in[10];
    const float* s4 = (const float*)d_in[11];
    const float* b4 = (const float*)d_in[12];
    const float* W5 = (const float*)d_in[13];
    const float* s5 = (const float*)d_in[14];
    const float* b5 = (const float*)d_in[15];
    const float* W6 = (const float*)d_in[16];
    const float* s6 = (const float*)d_in[17];
    const float* b6 = (const float*)d_in[18];
    const float* W7 = (const float*)d_in[19];
    const float* s7 = (const float*)d_in[20];
    const float* b7 = (const float*)d_in[21];
    const float* W8 = (const float*)d_in[22];
    const float* s8 = (const float*)d_in[23];
    const float* b8 = (const float*)d_in[24];
    const float* W9 = (const float*)d_in[25];
    const float* b9 = (const float*)d_in[26];
    float* out = (float*)d_out;

    float *nrm,*xcat,*PQ,*h7,*h8,*Wpq,*Gb; int* idx; unsigned* gmax;
    cudaGetSymbolAddress((void**)&nrm,  d_nrm);
    cudaGetSymbolAddress((void**)&idx,  d_idx);
    cudaGetSymbolAddress((void**)&xcat, d_xcat);
    cudaGetSymbolAddress((void**)&PQ,   d_PQ);
    cudaGetSymbolAddress((void**)&h7,   d_h7);
    cudaGetSymbolAddress((void**)&h8,   d_h8);
    cudaGetSymbolAddress((void**)&Wpq,  d_Wpq);
    cudaGetSymbolAddress((void**)&gmax, d_gmax);
    cudaGetSymbolAddress((void**)&Gb,   d_Gb);

    const float LK = 0.2f;

    nrm_kernel<<<64,256>>>(x, nrm);
    knn_kernel<<<BN_,256>>>(x, nrm, idx);

    // stage 1: P/Q from coords, fused edge conv (conv1+conv2) + max_k -> x1
    pq1_kernel<<<4096,256>>>(x, W1, PQ);
    fused_edge_tc<<<BN_,256>>>(PQ, s1, b1, W2, s2, b2, idx, xcat + 0, 192);

    // stage 2: P/Q = x1 * Wpq3, fused edge conv (conv3+conv4) + max_k -> x2
    wprep_kernel<<<32,256>>>(W3, Wpq);
    gemm_tc<<<dim3(128,1),256>>>(xcat, 192, Wpq, 64, nullptr, nullptr, nullptr,
                                 PQ, 128, nullptr, 64, 128, 1.f, 0);
    fused_edge_tc<<<BN_,256>>>(PQ, s3, b3, W4, s4, b4, idx, xcat + 64, 192);

    // stage 3: P/Q = x2 * Wpq5, gather + lrelu + max_k -> x3
    wprep_kernel<<<32,256>>>(W5, Wpq);
    gemm_tc<<<dim3(128,1),256>>>(xcat + 64, 192, Wpq, 64, nullptr, nullptr, nullptr,
                                 PQ, 128, nullptr, 64, 128, 1.f, 0);
    maxgather_kernel<<<4096,256>>>(PQ, s5, b5, idx, xcat + 128, 192);

    // conv6 (192 -> 1024) with fused max over N (atomic)
    init_gmax<<<16,256>>>(gmax);
    gemm_tc<<<dim3(128,8),256>>>(xcat, 192, W6, 192, s6, b6, nullptr,
                                 nullptr, 0, gmax, 192, 1024, LK, 2);

    // per-batch bias from g through W7's first 1024 input channels
    gb_kernel<<<8,256>>>(gmax, W7, Gb);

    // conv7: xcat (192) through W7[:,1024:] + Gb  -> h7 (512)
    gemm_tc<<<dim3(128,4),256>>>(xcat, 192, W7 + 1024, 1216, s7, b7, Gb,
                                 h7, 512, nullptr, 192, 512, LK, 0);
    // conv8: 512 -> 256
    gemm_tc<<<dim3(128,2),256>>>(h7, 512, W8, 512, s8, b8, nullptr,
                                 h8, 256, nullptr, 512, 256, LK, 0);
    // conv9: 256 -> 63, + bias, transposed store
    gemm128<<<dim3(128,1),256>>>(h8, 256, W9, 256, b9, out, 256, 63);
}

// round 4
// speedup vs baseline: 4.3134x; 1.6384x over previous
#include <cuda_runtime.h>
#include <float.h>
#include <stdint.h>

#define NBB 4
#define NNN 4096
#define NKK 40
#define BN_ (NBB*NNN)            // 16384
#define BNK (BN_*NKK)            // 655360
#define EDGE_PPB 8               // points per block in fused edge kernel

// ---------------- static scratch ----------------
__device__ float    d_nrm[BN_];
__device__ int      d_idx[BNK];
__device__ float    d_xcat[(size_t)BN_*192];   // [x1|x2|x3] per point
__device__ float    d_PQ[(size_t)BN_*128];     // P (0..63) | Q (64..127)
__device__ float    d_h7[(size_t)BN_*512];
__device__ float    d_h8[(size_t)BN_*256];
__device__ float    d_Wpq[128*64];
__device__ unsigned d_gmax[NBB*1024];
__device__ float    d_Gb[NBB*512];

__device__ __forceinline__ unsigned enc_f(float f){
    unsigned u = __float_as_uint(f);
    return (u & 0x80000000u) ? ~u : (u | 0x80000000u);
}
__device__ __forceinline__ float dec_f(unsigned k){
    unsigned u = (k & 0x80000000u) ? (k & 0x7FFFFFFFu) : ~k;
    return __uint_as_float(u);
}
__device__ __forceinline__ uint32_t f2tf(float f){
    uint32_t r; asm("cvt.rna.tf32.f32 %0, %1;" : "=r"(r) : "f"(f)); return r;
}
__device__ __forceinline__ void mma_tf32(float4 &c, const uint32_t* a, const uint32_t* b){
    asm volatile("mma.sync.aligned.m16n8k8.row.col.f32.tf32.tf32.f32 "
        "{%0,%1,%2,%3}, {%4,%5,%6,%7}, {%8,%9}, {%0,%1,%2,%3};"
        : "+f"(c.x), "+f"(c.y), "+f"(c.z), "+f"(c.w)
        : "r"(a[0]), "r"(a[1]), "r"(a[2]), "r"(a[3]), "r"(b[0]), "r"(b[1]));
}

// ---------------- squared norms ----------------
__global__ void nrm_kernel(const float* __restrict__ x, float* __restrict__ nrm){
    int i = blockIdx.x*256 + threadIdx.x;
    if (i >= BN_) return;
    int b = i >> 12, n = i & (NNN-1);
    const float* xb = x + (size_t)b*3*NNN;
    float a = xb[n], c = xb[NNN+n], d = xb[2*NNN+n];
    nrm[i] = a*a + c*c + d*d;
}

// ---------------- kNN via radix select (order-free top-40) -----------------
// Downstream of idx is always max-over-k, so any order of the top-40 set is valid.
__global__ void __launch_bounds__(256) knn_radix(const float* __restrict__ x,
                                                 const float* __restrict__ nrm,
                                                 int* __restrict__ idxo){
    __shared__ unsigned keys[NNN];
    __shared__ unsigned hist[256];
    __shared__ unsigned wtot[8];
    __shared__ unsigned sh_prefix;
    __shared__ int sh_remain;
    __shared__ int cnt_hi, cnt_eq;
    int blk = blockIdx.x;
    int b = blk >> 12;
    int n = blk & (NNN-1);
    int tid = threadIdx.x;
    int w = tid >> 5, lane = tid & 31;
    const float* xb = x + (size_t)b*3*NNN;
    const float* nb = nrm + b*NNN;
    float qx = xb[n], qy = xb[NNN+n], qz = xb[2*NNN+n];
    float qn = nb[n];
    for (int i = tid; i < NNN; i += 256){
        float d = 2.f*(qx*xb[i] + qy*xb[NNN+i] + qz*xb[2*NNN+i]) - qn - nb[i];
        keys[i] = enc_f(d);
    }
    if (tid == 0){ sh_prefix = 0; sh_remain = NKK; cnt_hi = 0; cnt_eq = 0; }
    __syncthreads();

    #pragma unroll
    for (int pass = 0; pass < 4; pass++){
        int shift = 24 - 8*pass;
        hist[tid] = 0;
        __syncthreads();
        unsigned pfx = sh_prefix;
        int remain = sh_remain;
        for (int i = tid; i < NNN; i += 256){
            unsigned k = keys[i];
            if (pass == 0 || (k >> (shift + 8)) == pfx)
                atomicAdd(&hist[(k >> shift) & 255], 1u);
        }
        __syncthreads();
        unsigned v = hist[tid];
        unsigned vv = v;
        #pragma unroll
        for (int off = 1; off < 32; off <<= 1){
            unsigned t = __shfl_down_sync(0xffffffffu, vv, off);
            if (lane + off < 32) vv += t;
        }
        if (lane == 0) wtot[w] = vv;
        __syncthreads();
        unsigned add = 0;
        for (int ww = w + 1; ww < 8; ww++) add += wtot[ww];
        unsigned suftid = vv + add;        // count of keys with bin >= tid
        unsigned above  = suftid - v;      // count with bin > tid
        if (suftid >= (unsigned)remain && above < (unsigned)remain){
            sh_prefix = (pfx << 8) | (unsigned)tid;
            sh_remain = remain - (int)above;
        }
        __syncthreads();
    }
    unsigned thr = sh_prefix;              // exact 40th-largest key
    int rem = sh_remain;                   // how many ==thr to include
    int* out = idxo + (size_t)blk*NKK;
    for (int i = tid; i < NNN; i += 256){
        if (keys[i] > thr){ int pos = atomicAdd(&cnt_hi, 1); out[pos] = i; }
    }
    __syncthreads();
    int base = cnt_hi;                     // == 40 - rem
    for (int i = tid; i < NNN; i += 256){
        if (keys[i] == thr){
            int pos = atomicAdd(&cnt_eq, 1);
            if (pos < rem) out[base + pos] = i;
        }
    }
}

// ---------------- P/Q from coords (stage 1) --------------------------------
__global__ void pq1_kernel(const float* __restrict__ x, const float* __restrict__ W1,
                           float* __restrict__ PQ){
    int i = blockIdx.x*256 + threadIdx.x;      // over BN_*64
    int c = i & 63; int p = i >> 6;
    int b = p >> 12, n = p & (NNN-1);
    const float* xb = x + (size_t)b*3*NNN + n;
    float x0 = xb[0], x1 = xb[NNN], x2 = xb[2*NNN];
    const float* w = W1 + c*6;
    float pv = x0*w[0] + x1*w[1] + x2*w[2];
    float qv = x0*(w[3]-w[0]) + x1*(w[4]-w[1]) + x2*(w[5]-w[2]);
    PQ[(size_t)p*128 + c]      = pv;
    PQ[(size_t)p*128 + 64 + c] = qv;
}

// ---------------- weight prep: W (64x128) -> Wpq (128x64) ------------------
__global__ void wprep_kernel(const float* __restrict__ W, float* __restrict__ Wpq){
    int i = blockIdx.x*256 + threadIdx.x;      // 8192
    int c = i & 63; int r = i >> 6;
    float v;
    if (r < 64) v = W[r*128 + c];
    else { int o = r - 64; v = W[o*128 + 64 + c] - W[o*128 + c]; }
    Wpq[r*64 + c] = v;
}

// ---------------- fused edge conv via tf32 mma, multi-point per block -------
// per point: build A[40][64] (gather+BN+lrelu), C = A * W2^T, BN+lrelu,
// max over 40 rows -> xout[64].  W2 loaded/converted once per block.
__global__ void __launch_bounds__(256) fused_edge_tc(
        const float* __restrict__ PQ,
        const float* __restrict__ sa, const float* __restrict__ ba,
        const float* __restrict__ W2,
        const float* __restrict__ sb, const float* __restrict__ bb,
        const int* __restrict__ idx, float* __restrict__ xout, int ostride)
{
    __shared__ uint32_t As[48][68];
    __shared__ uint32_t Ws[64][68];
    __shared__ float qrow[64], sav[64], bav[64];
    __shared__ int js[40];
    int tid = threadIdx.x;
    int w = tid >> 5, lane = tid & 31;
    int gid = lane >> 2, tig = lane & 3;

    for (int i = tid; i < 4096; i += 256) Ws[i>>6][i&63] = f2tf(W2[i]);
    if (tid < 64){ sav[tid] = sa[tid]; bav[tid] = ba[tid]; }
    // zero the pad rows (40..47) once
    for (int i = tid; i < 8*68; i += 256) As[40 + i/68][i%68] = 0u;

    int c0 = w*8 + 2*tig;
    float s0 = sb[c0], o0 = bb[c0], s1 = sb[c0+1], o1 = bb[c0+1];

    int p0 = blockIdx.x * EDGE_PPB;
    for (int it = 0; it < EDGE_PPB; it++){
        int p = p0 + it; int b = p >> 12;
        if (tid < 64) qrow[tid] = PQ[(size_t)p*128 + 64 + tid];
        if (tid < 40) js[tid] = idx[(size_t)p*NKK + tid];
        __syncthreads();
        int base = b << 12;
        for (int e = tid; e < 640; e += 256){
            int k = e >> 4, c4 = e & 15;
            float4 v4 = *(const float4*)&PQ[((size_t)(base + js[k]))*128 + c4*4];
            float4 q4 = *(const float4*)&qrow[c4*4];
            float4 sv = *(const float4*)&sav[c4*4];
            float4 bv = *(const float4*)&bav[c4*4];
            float z0 = sv.x*(v4.x+q4.x)+bv.x; z0 = z0>0.f? z0 : 0.2f*z0;
            float z1 = sv.y*(v4.y+q4.y)+bv.y; z1 = z1>0.f? z1 : 0.2f*z1;
            float z2 = sv.z*(v4.z+q4.z)+bv.z; z2 = z2>0.f? z2 : 0.2f*z2;
            float z3 = sv.w*(v4.w+q4.w)+bv.w; z3 = z3>0.f? z3 : 0.2f*z3;
            uint4 u = {f2tf(z0), f2tf(z1), f2tf(z2), f2tf(z3)};
            *(uint4*)&As[k][c4*4] = u;
        }
        __syncthreads();

        float4 acc[3];
        #pragma unroll
        for (int mt=0;mt<3;mt++) acc[mt] = make_float4(0.f,0.f,0.f,0.f);
        #pragma unroll
        for (int k0=0;k0<64;k0+=8){
            uint32_t bf[2];
            bf[0] = Ws[w*8+gid][k0+tig];
            bf[1] = Ws[w*8+gid][k0+tig+4];
            #pragma unroll
            for (int mt=0;mt<3;mt++){
                uint32_t af[4];
                int r = mt*16;
                af[0] = As[r+gid  ][k0+tig];
                af[1] = As[r+gid+8][k0+tig];
                af[2] = As[r+gid  ][k0+tig+4];
                af[3] = As[r+gid+8][k0+tig+4];
                mma_tf32(acc[mt], af, bf);
            }
        }
        float mx = -FLT_MAX, my = -FLT_MAX;
        #pragma unroll
        for (int mt=0;mt<3;mt++){
            float z;
            z = s0*acc[mt].x + o0; z = z>0.f? z : 0.2f*z; mx = fmaxf(mx, z);
            z = s1*acc[mt].y + o1; z = z>0.f? z : 0.2f*z; my = fmaxf(my, z);
            if (mt < 2){
                z = s0*acc[mt].z + o0; z = z>0.f? z : 0.2f*z; mx = fmaxf(mx, z);
                z = s1*acc[mt].w + o1; z = z>0.f? z : 0.2f*z; my = fmaxf(my, z);
            }
        }
        #pragma unroll
        for (int off=4; off<32; off<<=1){
            mx = fmaxf(mx, __shfl_xor_sync(0xffffffffu, mx, off));
            my = fmaxf(my, __shfl_xor_sync(0xffffffffu, my, off));
        }
        if (gid == 0){
            xout[(size_t)p*ostride + c0]     = mx;
            xout[(size_t)p*ostride + c0 + 1] = my;
        }
        __syncthreads();
    }
}

// ---------------- stage 3: gather + BN/lrelu + max_k -----------------------
__global__ void maxgather_kernel(const float* __restrict__ PQ,
                                 const float* __restrict__ s, const float* __restrict__ bias,
                                 const int* __restrict__ idx,
                                 float* __restrict__ xout, int ostride){
    int i = blockIdx.x*256 + threadIdx.x;   // BN_*64
    int o = i & 63, p = i >> 6; int b = p >> 12;
    float qv = PQ[(size_t)p*128 + 64 + o];
    float sc = s[o], bv = bias[o];
    const int* ip = idx + (size_t)p*NKK;
    size_t base = (size_t)(b << 12)*128;
    float m = -FLT_MAX;
    #pragma unroll 8
    for (int k=0;k<NKK;k++){
        float v = PQ[base + (size_t)ip[k]*128 + o] + qv;
        v = sc*v + bv;
        v = v>0.f? v : 0.2f*v;
        m = fmaxf(m, v);
    }
    xout[(size_t)p*ostride + o] = m;
}

__global__ void init_gmax(unsigned* g){
    int i = blockIdx.x*256 + threadIdx.x;
    if (i < NBB*1024) g[i] = 0u;
}

// ---------------- Gb[b][o] = sum_c g[b,c] * W7[o,c]  (c < 1024) ------------
__global__ void gb_kernel(const unsigned* __restrict__ gmax, const float* __restrict__ W7,
                          float* __restrict__ Gb){
    int i = blockIdx.x*256 + threadIdx.x;   // 2048
    int o = i & 511; int b = i >> 9;
    const unsigned* gm = gmax + b*1024;
    const float* w = W7 + (size_t)o*1216;
    float a0=0.f,a1=0.f,a2=0.f,a3=0.f;
    for (int c=0;c<1024;c+=4){
        a0 += dec_f(gm[c+0])*w[c+0];
        a1 += dec_f(gm[c+1])*w[c+1];
        a2 += dec_f(gm[c+2])*w[c+2];
        a3 += dec_f(gm[c+3])*w[c+3];
    }
    Gb[(size_t)b*512 + o] = (a0+a1)+(a2+a3);
}

// ---------------- tf32 tensor-core GEMM, 128x128 tile ----------------------
// C[m,n] = act( s[n]*(sum_k A[m,k]*W[n,k] + Gb[b,n]) + bias[n] )
// mode 0: store C.  mode 2: BN+lrelu then atomicMax over rows into gmax.
// Requires: Kd % 16 == 0, Nd % 128 == 0, M % 128 == 0.
__global__ void __launch_bounds__(256,2) gemm_tc(
        const float* __restrict__ A, int lda,
        const float* __restrict__ W, int ldw,
        const float* __restrict__ s, const float* __restrict__ bias,
        const float* __restrict__ Gb,
        float* __restrict__ C, int ldc, unsigned* gmax,
        int Kd, int Nd, float leak, int mode)
{
    __shared__ uint32_t As[128][20];
    __shared__ uint32_t Ws[128][20];
    int m0 = blockIdx.x*128, n0 = blockIdx.y*128;
    int tid = threadIdx.x, lane = tid & 31, w = tid >> 5;
    int gid = lane >> 2, tig = lane & 3;
    int wm = (w >> 2)*64, wn = (w & 3)*32;
    float4 acc[4][4];
    #pragma unroll
    for (int mt=0;mt<4;mt++)
        #pragma unroll
        for (int nt=0;nt<4;nt++) acc[mt][nt] = make_float4(0.f,0.f,0.f,0.f);

    int lr = tid >> 1, lq = (tid & 1)*8;
    const float* Ap = A + (size_t)(m0+lr)*lda + lq;
    const float* Wp = W + (size_t)(n0+lr)*ldw + lq;

    for (int k0 = 0; k0 < Kd; k0 += 16){
        float4 a0 = *(const float4*)(Ap + k0);
        float4 a1 = *(const float4*)(Ap + k0 + 4);
        float4 w0 = *(const float4*)(Wp + k0);
        float4 w1 = *(const float4*)(Wp + k0 + 4);
        uint4 ua0 = {f2tf(a0.x),f2tf(a0.y),f2tf(a0.z),f2tf(a0.w)};
        uint4 ua1 = {f2tf(a1.x),f2tf(a1.y),f2tf(a1.z),f2tf(a1.w)};
        uint4 uw0 = {f2tf(w0.x),f2tf(w0.y),f2tf(w0.z),f2tf(w0.w)};
        uint4 uw1 = {f2tf(w1.x),f2tf(w1.y),f2tf(w1.z),f2tf(w1.w)};
        *(uint4*)&As[lr][lq]   = ua0;
        *(uint4*)&As[lr][lq+4] = ua1;
        *(uint4*)&Ws[lr][lq]   = uw0;
        *(uint4*)&Ws[lr][lq+4] = uw1;
        __syncthreads();
        #pragma unroll
        for (int ks=0; ks<16; ks+=8){
            uint32_t bf[4][2];
            #pragma unroll
            for (int nt=0;nt<4;nt++){
                int n = wn + nt*8 + gid;
                bf[nt][0] = Ws[n][ks+tig];
                bf[nt][1] = Ws[n][ks+tig+4];
            }
            #pragma unroll
            for (int mt=0;mt<4;mt++){
                uint32_t af[4];
                int r = wm + mt*16;
                af[0] = As[r+gid  ][ks+tig];
                af[1] = As[r+gid+8][ks+tig];
                af[2] = As[r+gid  ][ks+tig+4];
                af[3] = As[r+gid+8][ks+tig+4];
                #pragma unroll
                for (int nt=0;nt<4;nt++) mma_tf32(acc[mt][nt], af, bf[nt]);
            }
        }
        __syncthreads();
    }

    int b = m0 >> 12;
    if (mode == 0){
        #pragma unroll
        for (int mt=0;mt<4;mt++){
            int r0 = m0 + wm + mt*16 + gid;
            #pragma unroll
            for (int nt=0;nt<4;nt++){
                int cg = n0 + wn + nt*8 + 2*tig;
                float gx = 0.f, gy = 0.f;
                if (Gb){ gx = Gb[(size_t)b*Nd + cg]; gy = Gb[(size_t)b*Nd + cg + 1]; }
                float sx=1.f, sy=1.f, bx=0.f, by=0.f;
                if (s){ sx=s[cg]; sy=s[cg+1]; bx=bias[cg]; by=bias[cg+1]; }
                else if (bias){ bx=bias[cg]; by=bias[cg+1]; }
                float4 a = acc[mt][nt];
                float z0 = sx*(a.x+gx)+bx; z0 = z0>0.f? z0 : leak*z0;
                float z1 = sy*(a.y+gy)+by; z1 = z1>0.f? z1 : leak*z1;
                float z2 = sx*(a.z+gx)+bx; z2 = z2>0.f? z2 : leak*z2;
                float z3 = sy*(a.w+gy)+by; z3 = z3>0.f? z3 : leak*z3;
                *(float2*)&C[(size_t)r0*ldc + cg]     = make_float2(z0,z1);
                *(float2*)&C[(size_t)(r0+8)*ldc + cg] = make_float2(z2,z3);
            }
        }
    } else {
        #pragma unroll
        for (int nt=0;nt<4;nt++){
            int cg = n0 + wn + nt*8 + 2*tig;
            float sx=s[cg], bx=bias[cg], sy=s[cg+1], by=bias[cg+1];
            float mx=-FLT_MAX, my=-FLT_MAX;
            #pragma unroll
            for (int mt=0;mt<4;mt++){
                float4 a = acc[mt][nt];
                float z;
                z = sx*a.x+bx; z = z>0.f? z : leak*z; mx = fmaxf(mx,z);
                z = sx*a.z+bx; z = z>0.f? z : leak*z; mx = fmaxf(mx,z);
                z = sy*a.y+by; z = z>0.f? z : leak*z; my = fmaxf(my,z);
                z = sy*a.w+by; z = z>0.f? z : leak*z; my = fmaxf(my,z);
            }
            #pragma unroll
            for (int off=4; off<32; off<<=1){
                mx = fmaxf(mx, __shfl_xor_sync(0xffffffffu, mx, off));
                my = fmaxf(my, __shfl_xor_sync(0xffffffffu, my, off));
            }
            if (gid == 0){
                atomicMax(&gmax[b*1024 + cg],     enc_f(mx));
                atomicMax(&gmax[b*1024 + cg + 1], enc_f(my));
            }
        }
    }
}

// ---------------- small fp32 GEMM kept for conv9 (transposed store) --------
__global__ void __launch_bounds__(256,2) gemm128(
        const float* __restrict__ A, int lda,
        const float* __restrict__ W, int ldw,
        const float* __restrict__ bias,
        float* __restrict__ C, int Kd, int Nd)
{
    __shared__ float As[8][132];
    __shared__ float Ws[8][132];
    int m0 = blockIdx.x*128, n0 = blockIdx.y*128;
    int tid = threadIdx.x;
    int hr = tid >> 1;
    int kq = (tid & 1)*4;
    const float* Ap = A + (size_t)(m0 + hr)*lda + kq;
    bool wval = (n0 + hr) < Nd;
    const float* Wp = W + (size_t)(n0 + (wval ? hr : 0))*ldw + kq;
    int tx = tid & 15, ty = tid >> 4;
    float acc[8][8];
    #pragma unroll
    for (int i=0;i<8;i++)
        #pragma unroll
        for (int j=0;j<8;j++) acc[i][j]=0.f;

    for (int k0 = 0; k0 < Kd; k0 += 8){
        float4 a4 = *(const float4*)(Ap + k0);
        float4 w4 = wval ? *(const float4*)(Wp + k0) : make_float4(0.f,0.f,0.f,0.f);
        As[kq+0][hr]=a4.x; As[kq+1][hr]=a4.y; As[kq+2][hr]=a4.z; As[kq+3][hr]=a4.w;
        Ws[kq+0][hr]=w4.x; Ws[kq+1][hr]=w4.y; Ws[kq+2][hr]=w4.z; Ws[kq+3][hr]=w4.w;
        __syncthreads();
        #pragma unroll
        for (int k=0;k<8;k++){
            float4 a0 = *(const float4*)&As[k][ty*4];
            float4 a1 = *(const float4*)&As[k][64+ty*4];
            float4 w0 = *(const float4*)&Ws[k][tx*4];
            float4 w1 = *(const float4*)&Ws[k][64+tx*4];
            float ar[8] = {a0.x,a0.y,a0.z,a0.w,a1.x,a1.y,a1.z,a1.w};
            float wr[8] = {w0.x,w0.y,w0.z,w0.w,w1.x,w1.y,w1.z,w1.w};
            #pragma unroll
            for (int i=0;i<8;i++)
                #pragma unroll
                for (int j=0;j<8;j++) acc[i][j] += ar[i]*wr[j];
        }
        __syncthreads();
    }
    #pragma unroll
    for (int i=0;i<8;i++){
        int m = m0 + (i<4 ? ty*4+i : 64 + ty*4 + (i-4));
        int bb_ = m >> 12, nn = m & (NNN-1);
        #pragma unroll
        for (int j=0;j<8;j++){
            int n = n0 + (j<4 ? tx*4+j : 64 + tx*4 + (j-4));
            if (n < Nd){
                float z = acc[i][j] + (bias ? bias[n] : 0.f);
                C[((size_t)bb_*Nd + n)*NNN + nn] = z;
            }
        }
    }
}

// ---------------------------------------------------------------------------
extern "C" void kernel_launch(void* const* d_in, const int* in_sizes, int n_in,
                              void* d_out, int out_size){
    const float* x  = (const float*)d_in[0];
    const float* W1 = (const float*)d_in[1];
    const float* s1 = (const float*)d_in[2];
    const float* b1 = (const float*)d_in[3];
    const float* W2 = (const float*)d_in[4];
    const float* s2 = (const float*)d_in[5];
    const float* b2 = (const float*)d_in[6];
    const float* W3 = (const float*)d_in[7];
    const float* s3 = (const float*)d_in[8];
    const float* b3 = (const float*)d_in[9];
    const float* W4 = (const float*)d_in[10];
    const float* s4 = (const float*)d_in[11];
    const float* b4 = (const float*)d_in[12];
    const float* W5 = (const float*)d_in[13];
    const float* s5 = (const float*)d_in[14];
    const float* b5 = (const float*)d_in[15];
    const float* W6 = (const float*)d_in[16];
    const float* s6 = (const float*)d_in[17];
    const float* b6 = (const float*)d_in[18];
    const float* W7 = (const float*)d_in[19];
    const float* s7 = (const float*)d_in[20];
    const float* b7 = (const float*)d_in[21];
    const float* W8 = (const float*)d_in[22];
    const float* s8 = (const float*)d_in[23];
    const float* b8 = (const float*)d_in[24];
    const float* W9 = (const float*)d_in[25];
    const float* b9 = (const float*)d_in[26];
    float* out = (float*)d_out;

    float *nrm,*xcat,*PQ,*h7,*h8,*Wpq,*Gb; int* idx; unsigned* gmax;
    cudaGetSymbolAddress((void**)&nrm,  d_nrm);
    cudaGetSymbolAddress((void**)&idx,  d_idx);
    cudaGetSymbolAddress((void**)&xcat, d_xcat);
    cudaGetSymbolAddress((void**)&PQ,   d_PQ);
    cudaGetSymbolAddress((void**)&h7,   d_h7);
    cudaGetSymbolAddress((void**)&h8,   d_h8);
    cudaGetSymbolAddress((void**)&Wpq,  d_Wpq);
    cudaGetSymbolAddress((void**)&gmax, d_gmax);
    cudaGetSymbolAddress((void**)&Gb,   d_Gb);

    const float LK = 0.2f;

    nrm_kernel<<<64,256>>>(x, nrm);
    knn_radix<<<BN_,256>>>(x, nrm, idx);

    // stage 1: P/Q from coords, fused edge conv (conv1+conv2) + max_k -> x1
    pq1_kernel<<<4096,256>>>(x, W1, PQ);
    fused_edge_tc<<<BN_/EDGE_PPB,256>>>(PQ, s1, b1, W2, s2, b2, idx, xcat + 0, 192);

    // stage 2: P/Q = x1 * Wpq3, fused edge conv (conv3+conv4) + max_k -> x2
    wprep_kernel<<<32,256>>>(W3, Wpq);
    gemm_tc<<<dim3(128,1),256>>>(xcat, 192, Wpq, 64, nullptr, nullptr, nullptr,
                                 PQ, 128, nullptr, 64, 128, 1.f, 0);
    fused_edge_tc<<<BN_/EDGE_PPB,256>>>(PQ, s3, b3, W4, s4, b4, idx, xcat + 64, 192);

    // stage 3: P/Q = x2 * Wpq5, gather + lrelu + max_k -> x3
    wprep_kernel<<<32,256>>>(W5, Wpq);
    gemm_tc<<<dim3(128,1),256>>>(xcat + 64, 192, Wpq, 64, nullptr, nullptr, nullptr,
                                 PQ, 128, nullptr, 64, 128, 1.f, 0);
    maxgather_kernel<<<4096,256>>>(PQ, s5, b5, idx, xcat + 128, 192);

    // conv6 (192 -> 1024) with fused max over N (atomic)
    init_gmax<<<16,256>>>(gmax);
    gemm_tc<<<dim3(128,8),256>>>(xcat, 192, W6, 192, s6, b6, nullptr,
                                 nullptr, 0, gmax, 192, 1024, LK, 2);

    // per-batch bias from g through W7's first 1024 input channels
    gb_kernel<<<8,256>>>(gmax, W7, Gb);

    // conv7: xcat (192) through W7[:,1024:] + Gb  -> h7 (512)
    gemm_tc<<<dim3(128,4),256>>>(xcat, 192, W7 + 1024, 1216, s7, b7, Gb,
                                 h7, 512, nullptr, 192, 512, LK, 0);
    // conv8: 512 -> 256
    gemm_tc<<<dim3(128,2),256>>>(h7, 512, W8, 512, s8, b8, nullptr,
                                 h8, 256, nullptr, 512, 256, LK, 0);
    // conv9: 256 -> 63, + bias, transposed store
    gemm128<<<dim3(128,1),256>>>(h8, 256, W9, 256, b9, out, 256, 63);
}

// round 5
// speedup vs baseline: 4.5011x; 1.0435x over previous
#include <cuda_runtime.h>
#include <float.h>
#include <stdint.h>

#define NBB 4
#define NNN 4096
#define NKK 40
#define BN_ (NBB*NNN)            // 16384
#define BNK (BN_*NKK)            // 655360
#define EDGE_PPT 2               // points per tile (A = 96 rows)
#define EDGE_ITER 4              // tiles per block -> 8 points per block

// ---------------- static scratch ----------------
__device__ float    d_nrm[BN_];
__device__ int      d_idx[BNK];
__device__ float    d_xcat[(size_t)BN_*192];   // [x1|x2|x3] per point
__device__ float    d_PQ[(size_t)BN_*128];     // P (0..63) | Q (64..127)
__device__ float    d_h7[(size_t)BN_*512];
__device__ float    d_h8[(size_t)BN_*256];
__device__ float    d_Wpq[128*64];
__device__ unsigned d_gmax[NBB*1024];
__device__ float    d_Gb[NBB*512];

__device__ __forceinline__ unsigned enc_f(float f){
    unsigned u = __float_as_uint(f);
    return (u & 0x80000000u) ? ~u : (u | 0x80000000u);
}
__device__ __forceinline__ float dec_f(unsigned k){
    unsigned u = (k & 0x80000000u) ? (k & 0x7FFFFFFFu) : ~k;
    return __uint_as_float(u);
}
__device__ __forceinline__ uint32_t f2tf(float f){
    uint32_t r; asm("cvt.rna.tf32.f32 %0, %1;" : "=r"(r) : "f"(f)); return r;
}
__device__ __forceinline__ void mma_tf32(float4 &c, const uint32_t* a, const uint32_t* b){
    asm volatile("mma.sync.aligned.m16n8k8.row.col.f32.tf32.tf32.f32 "
        "{%0,%1,%2,%3}, {%4,%5,%6,%7}, {%8,%9}, {%0,%1,%2,%3};"
        : "+f"(c.x), "+f"(c.y), "+f"(c.z), "+f"(c.w)
        : "r"(a[0]), "r"(a[1]), "r"(a[2]), "r"(a[3]), "r"(b[0]), "r"(b[1]));
}

// ---------------- squared norms ----------------
__global__ void nrm_kernel(const float* __restrict__ x, float* __restrict__ nrm){
    int i = blockIdx.x*256 + threadIdx.x;
    if (i >= BN_) return;
    int b = i >> 12, n = i & (NNN-1);
    const float* xb = x + (size_t)b*3*NNN;
    float a = xb[n], c = xb[NNN+n], d = xb[2*NNN+n];
    nrm[i] = a*a + c*c + d*d;
}

// ---------------- kNN via radix select (order-free top-40) -----------------
__global__ void __launch_bounds__(256) knn_radix(const float* __restrict__ x,
                                                 const float* __restrict__ nrm,
                                                 int* __restrict__ idxo){
    __shared__ unsigned keys[NNN];
    __shared__ unsigned hist[256];
    __shared__ unsigned wtot[8];
    __shared__ unsigned sh_prefix;
    __shared__ int sh_remain;
    __shared__ int cnt_hi, cnt_eq;
    int blk = blockIdx.x;
    int b = blk >> 12;
    int n = blk & (NNN-1);
    int tid = threadIdx.x;
    int w = tid >> 5, lane = tid & 31;
    const float* xb = x + (size_t)b*3*NNN;
    const float* nb = nrm + b*NNN;
    float qx = xb[n], qy = xb[NNN+n], qz = xb[2*NNN+n];
    float qn = nb[n];
    for (int i = tid; i < NNN; i += 256){
        float d = 2.f*(qx*xb[i] + qy*xb[NNN+i] + qz*xb[2*NNN+i]) - qn - nb[i];
        keys[i] = enc_f(d);
    }
    if (tid == 0){ sh_prefix = 0; sh_remain = NKK; cnt_hi = 0; cnt_eq = 0; }
    __syncthreads();

    #pragma unroll
    for (int pass = 0; pass < 4; pass++){
        int shift = 24 - 8*pass;
        hist[tid] = 0;
        __syncthreads();
        unsigned pfx = sh_prefix;
        int remain = sh_remain;
        for (int i = tid; i < NNN; i += 256){
            unsigned k = keys[i];
            if (pass == 0 || (k >> (shift + 8)) == pfx)
                atomicAdd(&hist[(k >> shift) & 255], 1u);
        }
        __syncthreads();
        unsigned v = hist[tid];
        unsigned vv = v;
        #pragma unroll
        for (int off = 1; off < 32; off <<= 1){
            unsigned t = __shfl_down_sync(0xffffffffu, vv, off);
            if (lane + off < 32) vv += t;
        }
        if (lane == 0) wtot[w] = vv;
        __syncthreads();
        unsigned add = 0;
        for (int ww = w + 1; ww < 8; ww++) add += wtot[ww];
        unsigned suftid = vv + add;
        unsigned above  = suftid - v;
        if (suftid >= (unsigned)remain && above < (unsigned)remain){
            sh_prefix = (pfx << 8) | (unsigned)tid;
            sh_remain = remain - (int)above;
        }
        __syncthreads();
    }
    unsigned thr = sh_prefix;
    int rem = sh_remain;
    int* out = idxo + (size_t)blk*NKK;
    for (int i = tid; i < NNN; i += 256){
        if (keys[i] > thr){ int pos = atomicAdd(&cnt_hi, 1); out[pos] = i; }
    }
    __syncthreads();
    int base = cnt_hi;
    for (int i = tid; i < NNN; i += 256){
        if (keys[i] == thr){
            int pos = atomicAdd(&cnt_eq, 1);
            if (pos < rem) out[base + pos] = i;
        }
    }
}

// ---------------- P/Q from coords (stage 1) --------------------------------
__global__ void pq1_kernel(const float* __restrict__ x, const float* __restrict__ W1,
                           float* __restrict__ PQ){
    int i = blockIdx.x*256 + threadIdx.x;
    int c = i & 63; int p = i >> 6;
    int b = p >> 12, n = p & (NNN-1);
    const float* xb = x + (size_t)b*3*NNN + n;
    float x0 = xb[0], x1 = xb[NNN], x2 = xb[2*NNN];
    const float* w = W1 + c*6;
    float pv = x0*w[0] + x1*w[1] + x2*w[2];
    float qv = x0*(w[3]-w[0]) + x1*(w[4]-w[1]) + x2*(w[5]-w[2]);
    PQ[(size_t)p*128 + c]      = pv;
    PQ[(size_t)p*128 + 64 + c] = qv;
}

// ---------------- weight prep: W (64x128) -> Wpq (128x64) ------------------
__global__ void wprep_kernel(const float* __restrict__ W, float* __restrict__ Wpq){
    int i = blockIdx.x*256 + threadIdx.x;
    int c = i & 63; int r = i >> 6;
    float v;
    if (r < 64) v = W[r*128 + c];
    else { int o = r - 64; v = W[o*128 + 64 + c] - W[o*128 + c]; }
    Wpq[r*64 + c] = v;
}

// ---------------- fused edge conv via tf32 mma, 2 points per tile ----------
// Warp (pt, wn): pt = w>>2 owns point pt of the tile; wn = w&3 owns 16 output
// channels. Per point, fragment LDS drops ~1.75x vs 1-point tiles.
__global__ void __launch_bounds__(256) fused_edge_tc(
        const float* __restrict__ PQ,
        const float* __restrict__ sa, const float* __restrict__ ba,
        const float* __restrict__ W2,
        const float* __restrict__ sb, const float* __restrict__ bb,
        const int* __restrict__ idx, float* __restrict__ xout, int ostride)
{
    __shared__ uint32_t As[96][68];
    __shared__ uint32_t Ws[64][68];
    __shared__ float qrow[2*64], sav[64], bav[64];
    __shared__ int js[2*40];
    int tid = threadIdx.x;
    int w = tid >> 5, lane = tid & 31;
    int gid = lane >> 2, tig = lane & 3;
    int pt = w >> 2, wn = w & 3;

    for (int i = tid; i < 4096; i += 256) Ws[i>>6][i&63] = f2tf(W2[i]);
    if (tid < 64){ sav[tid] = sa[tid]; bav[tid] = ba[tid]; }
    // zero pad rows (40..47, 88..95) once
    for (int i = tid; i < 8*68; i += 256){
        As[40 + i/68][i%68] = 0u;
        As[88 + i/68][i%68] = 0u;
    }

    // per-warp channel group: channels wn*16 + nt*8 + {gid rows of Ws}
    int c0 = wn*16 + 2*tig;   // epilogue channel pair base (with +8*nt)
    float se0 = sb[c0],   oe0 = bb[c0],   se1 = sb[c0+1],   oe1 = bb[c0+1];
    float se2 = sb[c0+8], oe2 = bb[c0+8], se3 = sb[c0+9],   oe3 = bb[c0+9];

    int p0 = blockIdx.x * (EDGE_PPT*EDGE_ITER);
    for (int it = 0; it < EDGE_ITER; it++){
        int pb = p0 + it*EDGE_PPT;
        if (tid < 128) qrow[tid] = PQ[(size_t)(pb + (tid>>6))*128 + 64 + (tid & 63)];
        if (tid < 80)  js[tid] = idx[(size_t)(pb + (tid>=40))*NKK + (tid>=40 ? tid-40 : tid)];
        __syncthreads();
        int base0 = ((pb)   >> 12) << 12;
        int base1 = ((pb+1) >> 12) << 12;
        for (int e = tid; e < 2*640; e += 256){
            int lpt = e >> 9 >> 1;            // e/1280? no: e in [0,1280)
            lpt = e / 640;
            int r = e - lpt*640;
            int k = r >> 4, c4 = r & 15;
            int bse = lpt ? base1 : base0;
            float4 v4 = *(const float4*)&PQ[((size_t)(bse + js[lpt*40 + k]))*128 + c4*4];
            float4 q4 = *(const float4*)&qrow[lpt*64 + c4*4];
            float4 sv = *(const float4*)&sav[c4*4];
            float4 bv = *(const float4*)&bav[c4*4];
            float z0 = sv.x*(v4.x+q4.x)+bv.x; z0 = z0>0.f? z0 : 0.2f*z0;
            float z1 = sv.y*(v4.y+q4.y)+bv.y; z1 = z1>0.f? z1 : 0.2f*z1;
            float z2 = sv.z*(v4.z+q4.z)+bv.z; z2 = z2>0.f? z2 : 0.2f*z2;
            float z3 = sv.w*(v4.w+q4.w)+bv.w; z3 = z3>0.f? z3 : 0.2f*z3;
            uint4 u = {f2tf(z0), f2tf(z1), f2tf(z2), f2tf(z3)};
            *(uint4*)&As[lpt*48 + k][c4*4] = u;
        }
        __syncthreads();

        float4 acc[3][2];
        #pragma unroll
        for (int mt=0;mt<3;mt++){ acc[mt][0]=make_float4(0.f,0.f,0.f,0.f);
                                  acc[mt][1]=make_float4(0.f,0.f,0.f,0.f); }
        int rbase = pt*48;
        #pragma unroll
        for (int k0=0;k0<64;k0+=8){
            uint32_t bf[2][2];
            #pragma unroll
            for (int nt=0;nt<2;nt++){
                bf[nt][0] = Ws[wn*16 + nt*8 + gid][k0+tig];
                bf[nt][1] = Ws[wn*16 + nt*8 + gid][k0+tig+4];
            }
            #pragma unroll
            for (int mt=0;mt<3;mt++){
                uint32_t af[4];
                int r = rbase + mt*16;
                af[0] = As[r+gid  ][k0+tig];
                af[1] = As[r+gid+8][k0+tig];
                af[2] = As[r+gid  ][k0+tig+4];
                af[3] = As[r+gid+8][k0+tig+4];
                mma_tf32(acc[mt][0], af, bf[0]);
                mma_tf32(acc[mt][1], af, bf[1]);
            }
        }
        // epilogue: BN + lrelu, max over valid rows (0..39 of this point)
        float m00=-FLT_MAX, m01=-FLT_MAX, m10=-FLT_MAX, m11=-FLT_MAX;
        #pragma unroll
        for (int mt=0;mt<3;mt++){
            float z;
            z = se0*acc[mt][0].x + oe0; z = z>0.f? z : 0.2f*z; m00 = fmaxf(m00, z);
            z = se1*acc[mt][0].y + oe1; z = z>0.f? z : 0.2f*z; m01 = fmaxf(m01, z);
            z = se2*acc[mt][1].x + oe2; z = z>0.f? z : 0.2f*z; m10 = fmaxf(m10, z);
            z = se3*acc[mt][1].y + oe3; z = z>0.f? z : 0.2f*z; m11 = fmaxf(m11, z);
            if (mt < 2){
                z = se0*acc[mt][0].z + oe0; z = z>0.f? z : 0.2f*z; m00 = fmaxf(m00, z);
                z = se1*acc[mt][0].w + oe1; z = z>0.f? z : 0.2f*z; m01 = fmaxf(m01, z);
                z = se2*acc[mt][1].z + oe2; z = z>0.f? z : 0.2f*z; m10 = fmaxf(m10, z);
                z = se3*acc[mt][1].w + oe3; z = z>0.f? z : 0.2f*z; m11 = fmaxf(m11, z);
            }
        }
        #pragma unroll
        for (int off=4; off<32; off<<=1){
            m00 = fmaxf(m00, __shfl_xor_sync(0xffffffffu, m00, off));
            m01 = fmaxf(m01, __shfl_xor_sync(0xffffffffu, m01, off));
            m10 = fmaxf(m10, __shfl_xor_sync(0xffffffffu, m10, off));
            m11 = fmaxf(m11, __shfl_xor_sync(0xffffffffu, m11, off));
        }
        if (gid == 0){
            int p = pb + pt;
            xout[(size_t)p*ostride + c0]     = m00;
            xout[(size_t)p*ostride + c0+1]   = m01;
            xout[(size_t)p*ostride + c0+8]   = m10;
            xout[(size_t)p*ostride + c0+9]   = m11;
        }
        __syncthreads();
    }
}

// ---------------- stage 3: gather + BN/lrelu + max_k -----------------------
__global__ void maxgather_kernel(const float* __restrict__ PQ,
                                 const float* __restrict__ s, const float* __restrict__ bias,
                                 const int* __restrict__ idx,
                                 float* __restrict__ xout, int ostride){
    int i = blockIdx.x*256 + threadIdx.x;
    int o = i & 63, p = i >> 6; int b = p >> 12;
    float qv = PQ[(size_t)p*128 + 64 + o];
    float sc = s[o], bv = bias[o];
    const int* ip = idx + (size_t)p*NKK;
    size_t base = (size_t)(b << 12)*128;
    float m = -FLT_MAX;
    #pragma unroll 8
    for (int k=0;k<NKK;k++){
        float v = PQ[base + (size_t)ip[k]*128 + o] + qv;
        v = sc*v + bv;
        v = v>0.f? v : 0.2f*v;
        m = fmaxf(m, v);
    }
    xout[(size_t)p*ostride + o] = m;
}

__global__ void init_gmax(unsigned* g){
    int i = blockIdx.x*256 + threadIdx.x;
    if (i < NBB*1024) g[i] = 0u;
}

// ---------------- Gb[b][o] = sum_c g[b,c] * W7[o,c]  (c < 1024) ------------
__global__ void gb_kernel(const unsigned* __restrict__ gmax, const float* __restrict__ W7,
                          float* __restrict__ Gb){
    int i = blockIdx.x*256 + threadIdx.x;
    int o = i & 511; int b = i >> 9;
    const unsigned* gm = gmax + b*1024;
    const float* w = W7 + (size_t)o*1216;
    float a0=0.f,a1=0.f,a2=0.f,a3=0.f;
    for (int c=0;c<1024;c+=4){
        a0 += dec_f(gm[c+0])*w[c+0];
        a1 += dec_f(gm[c+1])*w[c+1];
        a2 += dec_f(gm[c+2])*w[c+2];
        a3 += dec_f(gm[c+3])*w[c+3];
    }
    Gb[(size_t)b*512 + o] = (a0+a1)+(a2+a3);
}

// ---------------- tf32 tensor-core GEMM, 128x128 tile, double-buffered -----
__global__ void __launch_bounds__(256,2) gemm_tc(
        const float* __restrict__ A, int lda,
        const float* __restrict__ W, int ldw,
        const float* __restrict__ s, const float* __restrict__ bias,
        const float* __restrict__ Gb,
        float* __restrict__ C, int ldc, unsigned* gmax,
        int Kd, int Nd, float leak, int mode)
{
    __shared__ uint32_t As[2][128][20];
    __shared__ uint32_t Ws[2][128][20];
    int m0 = blockIdx.x*128, n0 = blockIdx.y*128;
    int tid = threadIdx.x, lane = tid & 31, w = tid >> 5;
    int gid = lane >> 2, tig = lane & 3;
    int wm = (w >> 2)*64, wn = (w & 3)*32;
    float4 acc[4][4];
    #pragma unroll
    for (int mt=0;mt<4;mt++)
        #pragma unroll
        for (int nt=0;nt<4;nt++) acc[mt][nt] = make_float4(0.f,0.f,0.f,0.f);

    int lr = tid >> 1, lq = (tid & 1)*8;
    const float* Ap = A + (size_t)(m0+lr)*lda + lq;
    const float* Wp = W + (size_t)(n0+lr)*ldw + lq;

    int nk = Kd >> 4;
    float4 ta0 = *(const float4*)(Ap);
    float4 ta1 = *(const float4*)(Ap + 4);
    float4 tw0 = *(const float4*)(Wp);
    float4 tw1 = *(const float4*)(Wp + 4);
    {
        uint4 ua0 = {f2tf(ta0.x),f2tf(ta0.y),f2tf(ta0.z),f2tf(ta0.w)};
        uint4 ua1 = {f2tf(ta1.x),f2tf(ta1.y),f2tf(ta1.z),f2tf(ta1.w)};
        uint4 uw0 = {f2tf(tw0.x),f2tf(tw0.y),f2tf(tw0.z),f2tf(tw0.w)};
        uint4 uw1 = {f2tf(tw1.x),f2tf(tw1.y),f2tf(tw1.z),f2tf(tw1.w)};
        *(uint4*)&As[0][lr][lq]   = ua0;
        *(uint4*)&As[0][lr][lq+4] = ua1;
        *(uint4*)&Ws[0][lr][lq]   = uw0;
        *(uint4*)&Ws[0][lr][lq+4] = uw1;
    }
    __syncthreads();

    for (int c = 0; c < nk; c++){
        int cur = c & 1;
        if (c + 1 < nk){
            int k0 = (c+1) << 4;
            ta0 = *(const float4*)(Ap + k0);
            ta1 = *(const float4*)(Ap + k0 + 4);
            tw0 = *(const float4*)(Wp + k0);
            tw1 = *(const float4*)(Wp + k0 + 4);
        }
        #pragma unroll
        for (int ks=0; ks<16; ks+=8){
            uint32_t bf[4][2];
            #pragma unroll
            for (int nt=0;nt<4;nt++){
                int n = wn + nt*8 + gid;
                bf[nt][0] = Ws[cur][n][ks+tig];
                bf[nt][1] = Ws[cur][n][ks+tig+4];
            }
            #pragma unroll
            for (int mt=0;mt<4;mt++){
                uint32_t af[4];
                int r = wm + mt*16;
                af[0] = As[cur][r+gid  ][ks+tig];
                af[1] = As[cur][r+gid+8][ks+tig];
                af[2] = As[cur][r+gid  ][ks+tig+4];
                af[3] = As[cur][r+gid+8][ks+tig+4];
                #pragma unroll
                for (int nt=0;nt<4;nt++) mma_tf32(acc[mt][nt], af, bf[nt]);
            }
        }
        if (c + 1 < nk){
            int nxt = cur ^ 1;
            uint4 ua0 = {f2tf(ta0.x),f2tf(ta0.y),f2tf(ta0.z),f2tf(ta0.w)};
            uint4 ua1 = {f2tf(ta1.x),f2tf(ta1.y),f2tf(ta1.z),f2tf(ta1.w)};
            uint4 uw0 = {f2tf(tw0.x),f2tf(tw0.y),f2tf(tw0.z),f2tf(tw0.w)};
            uint4 uw1 = {f2tf(tw1.x),f2tf(tw1.y),f2tf(tw1.z),f2tf(tw1.w)};
            *(uint4*)&As[nxt][lr][lq]   = ua0;
            *(uint4*)&As[nxt][lr][lq+4] = ua1;
            *(uint4*)&Ws[nxt][lr][lq]   = uw0;
            *(uint4*)&Ws[nxt][lr][lq+4] = uw1;
            __syncthreads();
        }
    }

    int b = m0 >> 12;
    if (mode == 0){
        #pragma unroll
        for (int mt=0;mt<4;mt++){
            int r0 = m0 + wm + mt*16 + gid;
            #pragma unroll
            for (int nt=0;nt<4;nt++){
                int cg = n0 + wn + nt*8 + 2*tig;
                float gx = 0.f, gy = 0.f;
                if (Gb){ gx = Gb[(size_t)b*Nd + cg]; gy = Gb[(size_t)b*Nd + cg + 1]; }
                float sx=1.f, sy=1.f, bx=0.f, by=0.f;
                if (s){ sx=s[cg]; sy=s[cg+1]; bx=bias[cg]; by=bias[cg+1]; }
                else if (bias){ bx=bias[cg]; by=bias[cg+1]; }
                float4 a = acc[mt][nt];
                float z0 = sx*(a.x+gx)+bx; z0 = z0>0.f? z0 : leak*z0;
                float z1 = sy*(a.y+gy)+by; z1 = z1>0.f? z1 : leak*z1;
                float z2 = sx*(a.z+gx)+bx; z2 = z2>0.f? z2 : leak*z2;
                float z3 = sy*(a.w+gy)+by; z3 = z3>0.f? z3 : leak*z3;
                *(float2*)&C[(size_t)r0*ldc + cg]     = make_float2(z0,z1);
                *(float2*)&C[(size_t)(r0+8)*ldc + cg] = make_float2(z2,z3);
            }
        }
    } else {
        #pragma unroll
        for (int nt=0;nt<4;nt++){
            int cg = n0 + wn + nt*8 + 2*tig;
            float sx=s[cg], bx=bias[cg], sy=s[cg+1], by=bias[cg+1];
            float mx=-FLT_MAX, my=-FLT_MAX;
            #pragma unroll
            for (int mt=0;mt<4;mt++){
                float4 a = acc[mt][nt];
                float z;
                z = sx*a.x+bx; z = z>0.f? z : leak*z; mx = fmaxf(mx,z);
                z = sx*a.z+bx; z = z>0.f? z : leak*z; mx = fmaxf(mx,z);
                z = sy*a.y+by; z = z>0.f? z : leak*z; my = fmaxf(my,z);
                z = sy*a.w+by; z = z>0.f? z : leak*z; my = fmaxf(my,z);
            }
            #pragma unroll
            for (int off=4; off<32; off<<=1){
                mx = fmaxf(mx, __shfl_xor_sync(0xffffffffu, mx, off));
                my = fmaxf(my, __shfl_xor_sync(0xffffffffu, my, off));
            }
            if (gid == 0){
                atomicMax(&gmax[b*1024 + cg],     enc_f(mx));
                atomicMax(&gmax[b*1024 + cg + 1], enc_f(my));
            }
        }
    }
}

// ---------------- small fp32 GEMM kept for conv9 (transposed store) --------
__global__ void __launch_bounds__(256,2) gemm128(
        const float* __restrict__ A, int lda,
        const float* __restrict__ W, int ldw,
        const float* __restrict__ bias,
        float* __restrict__ C, int Kd, int Nd)
{
    __shared__ float As[8][132];
    __shared__ float Ws[8][132];
    int m0 = blockIdx.x*128, n0 = blockIdx.y*128;
    int tid = threadIdx.x;
    int hr = tid >> 1;
    int kq = (tid & 1)*4;
    const float* Ap = A + (size_t)(m0 + hr)*lda + kq;
    bool wval = (n0 + hr) < Nd;
    const float* Wp = W + (size_t)(n0 + (wval ? hr : 0))*ldw + kq;
    int tx = tid & 15, ty = tid >> 4;
    float acc[8][8];
    #pragma unroll
    for (int i=0;i<8;i++)
        #pragma unroll
        for (int j=0;j<8;j++) acc[i][j]=0.f;

    for (int k0 = 0; k0 < Kd; k0 += 8){
        float4 a4 = *(const float4*)(Ap + k0);
        float4 w4 = wval ? *(const float4*)(Wp + k0) : make_float4(0.f,0.f,0.f,0.f);
        As[kq+0][hr]=a4.x; As[kq+1][hr]=a4.y; As[kq+2][hr]=a4.z; As[kq+3][hr]=a4.w;
        Ws[kq+0][hr]=w4.x; Ws[kq+1][hr]=w4.y; Ws[kq+2][hr]=w4.z; Ws[kq+3][hr]=w4.w;
        __syncthreads();
        #pragma unroll
        for (int k=0;k<8;k++){
            float4 a0 = *(const float4*)&As[k][ty*4];
            float4 a1 = *(const float4*)&As[k][64+ty*4];
            float4 w0 = *(const float4*)&Ws[k][tx*4];
            float4 w1 = *(const float4*)&Ws[k][64+tx*4];
            float ar[8] = {a0.x,a0.y,a0.z,a0.w,a1.x,a1.y,a1.z,a1.w};
            float wr[8] = {w0.x,w0.y,w0.z,w0.w,w1.x,w1.y,w1.z,w1.w};
            #pragma unroll
            for (int i=0;i<8;i++)
                #pragma unroll
                for (int j=0;j<8;j++) acc[i][j] += ar[i]*wr[j];
        }
        __syncthreads();
    }
    #pragma unroll
    for (int i=0;i<8;i++){
        int m = m0 + (i<4 ? ty*4+i : 64 + ty*4 + (i-4));
        int bb_ = m >> 12, nn = m & (NNN-1);
        #pragma unroll
        for (int j=0;j<8;j++){
            int n = n0 + (j<4 ? tx*4+j : 64 + tx*4 + (j-4));
            if (n < Nd){
                float z = acc[i][j] + (bias ? bias[n] : 0.f);
                C[((size_t)bb_*Nd + n)*NNN + nn] = z;
            }
        }
    }
}

// ---------------------------------------------------------------------------
extern "C" void kernel_launch(void* const* d_in, const int* in_sizes, int n_in,
                              void* d_out, int out_size){
    const float* x  = (const float*)d_in[0];
    const float* W1 = (const float*)d_in[1];
    const float* s1 = (const float*)d_in[2];
    const float* b1 = (const float*)d_in[3];
    const float* W2 = (const float*)d_in[4];
    const float* s2 = (const float*)d_in[5];
    const float* b2 = (const float*)d_in[6];
    const float* W3 = (const float*)d_in[7];
    const float* s3 = (const float*)d_in[8];
    const float* b3 = (const float*)d_in[9];
    const float* W4 = (const float*)d_in[10];
    const float* s4 = (const float*)d_in[11];
    const float* b4 = (const float*)d_in[12];
    const float* W5 = (const float*)d_in[13];
    const float* s5 = (const float*)d_in[14];
    const float* b5 = (const float*)d_in[15];
    const float* W6 = (const float*)d_in[16];
    const float* s6 = (const float*)d_in[17];
    const float* b6 = (const float*)d_in[18];
    const float* W7 = (const float*)d_in[19];
    const float* s7 = (const float*)d_in[20];
    const float* b7 = (const float*)d_in[21];
    const float* W8 = (const float*)d_in[22];
    const float* s8 = (const float*)d_in[23];
    const float* b8 = (const float*)d_in[24];
    const float* W9 = (const float*)d_in[25];
    const float* b9 = (const float*)d_in[26];
    float* out = (float*)d_out;

    float *nrm,*xcat,*PQ,*h7,*h8,*Wpq,*Gb; int* idx; unsigned* gmax;
    cudaGetSymbolAddress((void**)&nrm,  d_nrm);
    cudaGetSymbolAddress((void**)&idx,  d_idx);
    cudaGetSymbolAddress((void**)&xcat, d_xcat);
    cudaGetSymbolAddress((void**)&PQ,   d_PQ);
    cudaGetSymbolAddress((void**)&h7,   d_h7);
    cudaGetSymbolAddress((void**)&h8,   d_h8);
    cudaGetSymbolAddress((void**)&Wpq,  d_Wpq);
    cudaGetSymbolAddress((void**)&gmax, d_gmax);
    cudaGetSymbolAddress((void**)&Gb,   d_Gb);

    const float LK = 0.2f;
    const int edge_blocks = BN_/(EDGE_PPT*EDGE_ITER);

    nrm_kernel<<<64,256>>>(x, nrm);
    knn_radix<<<BN_,256>>>(x, nrm, idx);

    // stage 1: P/Q from coords, fused edge conv (conv1+conv2) + max_k -> x1
    pq1_kernel<<<4096,256>>>(x, W1, PQ);
    fused_edge_tc<<<edge_blocks,256>>>(PQ, s1, b1, W2, s2, b2, idx, xcat + 0, 192);

    // stage 2: P/Q = x1 * Wpq3, fused edge conv (conv3+conv4) + max_k -> x2
    wprep_kernel<<<32,256>>>(W3, Wpq);
    gemm_tc<<<dim3(128,1),256>>>(xcat, 192, Wpq, 64, nullptr, nullptr, nullptr,
                                 PQ, 128, nullptr, 64, 128, 1.f, 0);
    fused_edge_tc<<<edge_blocks,256>>>(PQ, s3, b3, W4, s4, b4, idx, xcat + 64, 192);

    // stage 3: P/Q = x2 * Wpq5, gather + lrelu + max_k -> x3
    wprep_kernel<<<32,256>>>(W5, Wpq);
    gemm_tc<<<dim3(128,1),256>>>(xcat + 64, 192, Wpq, 64, nullptr, nullptr, nullptr,
                                 PQ, 128, nullptr, 64, 128, 1.f, 0);
    maxgather_kernel<<<4096,256>>>(PQ, s5, b5, idx, xcat + 128, 192);

    // conv6 (192 -> 1024) with fused max over N (atomic)
    init_gmax<<<16,256>>>(gmax);
    gemm_tc<<<dim3(128,8),256>>>(xcat, 192, W6, 192, s6, b6, nullptr,
                                 nullptr, 0, gmax, 192, 1024, LK, 2);

    // per-batch bias from g through W7's first 1024 input channels
    gb_kernel<<<8,256>>>(gmax, W7, Gb);

    // conv7: xcat (192) through W7[:,1024:] + Gb  -> h7 (512)
    gemm_tc<<<dim3(128,4),256>>>(xcat, 192, W7 + 1024, 1216, s7, b7, Gb,
                                 h7, 512, nullptr, 192, 512, LK, 0);
    // conv8: 512 -> 256
    gemm_tc<<<dim3(128,2),256>>>(h7, 512, W8, 512, s8, b8, nullptr,
                                 h8, 256, nullptr, 512, 256, LK, 0);
    // conv9: 256 -> 63, + bias, transposed store
    gemm128<<<dim3(128,1),256>>>(h8, 256, W9, 256, b9, out, 256, 63);
}